// round 3
// baseline (speedup 1.0000x reference)
#include <cuda_runtime.h>
#include <math_constants.h>

#define BATCH 32
#define CDIM 256
#define HW 4096
#define NCODES 1024
#define NPIX (BATCH * HW)

#define PIX_TILE 128
#define CK 32

// packed f32x2 helpers (two independent IEEE fp32 ops per instruction)
#define PACK2(d, lo, hi) \
    asm("mov.b64 %0, {%1, %2};" : "=l"(d) : "f"(lo), "f"(hi))
#define UNPACK2(lo, hi, s) \
    asm("mov.b64 {%0, %1}, %2;" : "=f"(lo), "=f"(hi) : "l"(s))
#define FMA2(d, a, b, c) \
    asm("fma.rn.f32x2 %0, %1, %2, %3;" : "=l"(d) : "l"(a), "l"(b), "l"(c))

// ---------------- scratch ----------------
__device__ float g_enorm[NCODES];

// ---------------- ||e_k||^2 : strict sequential, round-per-op (no FMA) ----------------
__global__ void enorm_kernel(const float* __restrict__ cb) {
    int k = blockIdx.x * blockDim.x + threadIdx.x;
    if (k >= NCODES) return;
    float acc = 0.f;
    const float* row = cb + k * CDIM;
    for (int c = 0; c < CDIM; ++c) {
        float v = row[c];
        acc = __fadd_rn(acc, __fmul_rn(v, v));
    }
    g_enorm[k] = acc;
}

// ---------------- main VQ kernel ----------------
// smem layout (floats):
//   [0, 33792)     Zs[c][p] (256x128, 32768 used); reused as gbuf[c][p] pitch 132
//   [33792, 41984) bs: double-buffered codebook chunk 2 x (32 x 128)
//   [41984, 44032) rval: 128 x 16
//   [44032, 46080) ridx: 128 x 16 (int)
//   [46080, 46208) idxf: 128 (int)
//   [46208, 46336) zns: 128
#define SM_ZS    0
#define SM_BS    33792
#define SM_RVAL  41984
#define SM_RIDX  44032
#define SM_IDXF  46080
#define SM_ZNS   46208
#define SM_TOTAL_FLOATS 46336

extern __shared__ float smem[];

__global__ __launch_bounds__(256, 1)
void vq_kernel(const float* __restrict__ z, const float* __restrict__ cb,
               float* __restrict__ out) {
    float* Zs   = smem + SM_ZS;
    float* bs   = smem + SM_BS;
    float* rval = smem + SM_RVAL;
    int*   ridx = (int*)(smem + SM_RIDX);
    int*   idxf = (int*)(smem + SM_IDXF);
    float* zns  = smem + SM_ZNS;

    const int tid = threadIdx.x;
    const int tx = tid & 15;       // code sub-block
    const int ty = tid >> 4;       // pixel sub-block

    const int pb = blockIdx.x;     // 1024 blocks, 128 pixels each
    const int b  = pb >> 5;
    const int o4 = ((pb & 31) * PIX_TILE) >> 2;

    const float4* zg4  = (const float4*)z + (size_t)b * (CDIM * HW / 4);
    float4*       out4 = (float4*)out      + (size_t)b * (CDIM * HW / 4);
    const float4* cb4  = (const float4*)cb;

    // ---- stage z tile: Zs[c][p], fully coalesced ----
    for (int j = tid; j < CDIM * (PIX_TILE / 4); j += 256) {
        int c = j >> 5, v = j & 31;
        *(float4*)&Zs[c * PIX_TILE + v * 4] = zg4[c * (HW / 4) + o4 + v];
    }
    __syncthreads();

    // ---- ||z||^2 per pixel: strict sequential ascending-c, round-per-op ----
    if (tid < PIX_TILE) {
        float acc = 0.f;
        for (int c = 0; c < CDIM; ++c) {
            float v = Zs[c * PIX_TILE + tid];
            acc = __fadd_rn(acc, __fmul_rn(v, v));
        }
        zns[tid] = acc;
    }
    __syncthreads();

    float minv[8];
    int   mini[8];
    #pragma unroll
    for (int p = 0; p < 8; ++p) { minv[p] = CUDART_INF_F; mini[p] = 0x7fffffff; }

    const int kk = tid >> 1;       // 0..127 code row within tile
    const int part = tid & 1;      // which 16-float half of the 32-c chunk

    float znp[8];
    #pragma unroll
    for (int p = 0; p < 8; ++p) znp[p] = zns[ty * 8 + p];

    for (int kt = 0; kt < 8; ++kt) {
        const int k0 = kt * 128;
        // packed accumulators: acc2[pp][q] holds (p=2*pp, p=2*pp+1) for code q
        unsigned long long acc2[4][8];
        #pragma unroll
        for (int pp = 0; pp < 4; ++pp)
            #pragma unroll
            for (int q = 0; q < 8; ++q) acc2[pp][q] = 0ull;

        // prefetch chunk 0 of this code tile (16 floats/thread)
        float4 r0, r1, r2, r3;
        {
            const float* src = &cb[(k0 + kk) * CDIM + part * 16];
            r0 = *(const float4*)src;        r1 = *(const float4*)(src + 4);
            r2 = *(const float4*)(src + 8);  r3 = *(const float4*)(src + 12);
        }

        for (int cc = 0; cc < CDIM / CK; ++cc) {
            float* buf = &bs[(cc & 1) * (CK * 128)];
            {   // transpose-store chunk into smem: bs[s][kk]
                int sb = part * 16;
                buf[(sb +  0) * 128 + kk] = r0.x; buf[(sb +  1) * 128 + kk] = r0.y;
                buf[(sb +  2) * 128 + kk] = r0.z; buf[(sb +  3) * 128 + kk] = r0.w;
                buf[(sb +  4) * 128 + kk] = r1.x; buf[(sb +  5) * 128 + kk] = r1.y;
                buf[(sb +  6) * 128 + kk] = r1.z; buf[(sb +  7) * 128 + kk] = r1.w;
                buf[(sb +  8) * 128 + kk] = r2.x; buf[(sb +  9) * 128 + kk] = r2.y;
                buf[(sb + 10) * 128 + kk] = r2.z; buf[(sb + 11) * 128 + kk] = r2.w;
                buf[(sb + 12) * 128 + kk] = r3.x; buf[(sb + 13) * 128 + kk] = r3.y;
                buf[(sb + 14) * 128 + kk] = r3.z; buf[(sb + 15) * 128 + kk] = r3.w;
            }
            __syncthreads();
            if (cc < CDIM / CK - 1) {   // prefetch next chunk (overlaps compute)
                const float* src = &cb[(k0 + kk) * CDIM + (cc + 1) * CK + part * 16];
                r0 = *(const float4*)src;        r1 = *(const float4*)(src + 4);
                r2 = *(const float4*)(src + 8);  r3 = *(const float4*)(src + 12);
            }
            // strictly ascending c; each (p,q) is one fused-FMA accumulator chain.
            // fma.rn.f32x2 = two independent IEEE fp32 FMAs -> bit-identical per lane.
            #pragma unroll 16
            for (int s = 0; s < CK; ++s) {
                const float* zr = &Zs[((cc << 5) + s) * PIX_TILE + (ty << 3)];
                float4 a0 = *(const float4*)zr;
                float4 a1 = *(const float4*)(zr + 4);
                const float* br = &buf[s * 128 + (tx << 3)];
                float4 b0 = *(const float4*)br;
                float4 b1 = *(const float4*)(br + 4);

                unsigned long long pa[4], pb[8];
                PACK2(pa[0], a0.x, a0.y);  PACK2(pa[1], a0.z, a0.w);
                PACK2(pa[2], a1.x, a1.y);  PACK2(pa[3], a1.z, a1.w);
                PACK2(pb[0], b0.x, b0.x);  PACK2(pb[1], b0.y, b0.y);
                PACK2(pb[2], b0.z, b0.z);  PACK2(pb[3], b0.w, b0.w);
                PACK2(pb[4], b1.x, b1.x);  PACK2(pb[5], b1.y, b1.y);
                PACK2(pb[6], b1.z, b1.z);  PACK2(pb[7], b1.w, b1.w);

                #pragma unroll
                for (int pp = 0; pp < 4; ++pp)
                    #pragma unroll
                    for (int q = 0; q < 8; ++q)
                        FMA2(acc2[pp][q], pa[pp], pb[q], acc2[pp][q]);
            }
            __syncthreads();
        }

        // ---- running min update for this code tile ----
        // d = fl( fl(zn + en) - fl(2*dot) )
        float en[8];
        #pragma unroll
        for (int q = 0; q < 8; ++q) en[q] = g_enorm[k0 + tx * 8 + q];
        #pragma unroll
        for (int pp = 0; pp < 4; ++pp) {
            #pragma unroll
            for (int q = 0; q < 8; ++q) {
                float dlo, dhi;
                UNPACK2(dlo, dhi, acc2[pp][q]);
                int p0 = 2 * pp, p1 = 2 * pp + 1;
                float s0 = __fsub_rn(__fadd_rn(znp[p0], en[q]), __fmul_rn(2.0f, dlo));
                float s1 = __fsub_rn(__fadd_rn(znp[p1], en[q]), __fmul_rn(2.0f, dhi));
                int ki = k0 + tx * 8 + q;
                if (s0 < minv[p0]) { minv[p0] = s0; mini[p0] = ki; }
                if (s1 < minv[p1]) { minv[p1] = s1; mini[p1] = ki; }
            }
        }
    }

    // ---- cross-thread (tx) reduction: lexicographic (value, lowest index) ----
    #pragma unroll
    for (int p = 0; p < 8; ++p) {
        rval[(ty * 8 + p) * 16 + tx] = minv[p];
        ridx[(ty * 8 + p) * 16 + tx] = mini[p];
    }
    __syncthreads();
    if (tid < PIX_TILE) {
        float bv = rval[tid * 16];
        int   bi = ridx[tid * 16];
        #pragma unroll
        for (int i = 1; i < 16; ++i) {
            float v = rval[tid * 16 + i];
            int   x = ridx[tid * 16 + i];
            if (v < bv || (v == bv && x < bi)) { bv = v; bi = x; }
        }
        idxf[tid] = bi;
    }
    __syncthreads();

    // ---- gather codebook rows into gbuf[c][p] (pitch 132, reuses Zs space) ----
    float* gbuf = smem + SM_ZS;
    for (int j = tid; j < PIX_TILE * (CDIM / 4); j += 256) {
        int p = j >> 6, v = j & 63;
        float4 e = cb4[idxf[p] * (CDIM / 4) + v];
        int c = v * 4;
        gbuf[(c + 0) * 132 + p] = e.x;
        gbuf[(c + 1) * 132 + p] = e.y;
        gbuf[(c + 2) * 132 + p] = e.z;
        gbuf[(c + 3) * 132 + p] = e.w;
    }
    __syncthreads();

    // ---- write NCHW output, reproducing straight-through fp32 rounding ----
    for (int i = tid; i < CDIM * (PIX_TILE / 4); i += 256) {
        int c = i >> 5, v = i & 31;
        float4 q  = *(const float4*)&gbuf[c * 132 + v * 4];
        float4 zv = zg4[c * (HW / 4) + o4 + v];
        float4 o;
        o.x = __fadd_rn(zv.x, __fsub_rn(q.x, zv.x));
        o.y = __fadd_rn(zv.y, __fsub_rn(q.y, zv.y));
        o.z = __fadd_rn(zv.z, __fsub_rn(q.z, zv.z));
        o.w = __fadd_rn(zv.w, __fsub_rn(q.w, zv.w));
        out4[c * (HW / 4) + o4 + v] = o;
    }
}

// ---------------- launch ----------------
extern "C" void kernel_launch(void* const* d_in, const int* in_sizes, int n_in,
                              void* d_out, int out_size) {
    const float* z  = (const float*)d_in[0];   // [32, 256, 64, 64]
    const float* cb = (const float*)d_in[1];   // [1024, 256]
    float* out = (float*)d_out;

    cudaFuncSetAttribute(vq_kernel, cudaFuncAttributeMaxDynamicSharedMemorySize,
                         SM_TOTAL_FLOATS * 4);

    enorm_kernel<<<NCODES / 256, 256>>>(cb);
    vq_kernel<<<NPIX / PIX_TILE, 256, SM_TOTAL_FLOATS * 4>>>(z, cb, out);
}

// round 5
// speedup vs baseline: 1.2897x; 1.2897x over previous
#include <cuda_runtime.h>
#include <cuda_bf16.h>
#include <math_constants.h>
#include <cstdint>

#define BATCH 32
#define CDIM 256
#define HW 4096
#define NCODES 1024
#define NPIX (BATCH * HW)
#define PIX_TILE 128
#define THRESH 2.5e-4f

// ---------------- PTX helpers (baseline PTX only: sm_80-class, no 'a' features) ----
__device__ __forceinline__ uint32_t smem_u32(const void* p) {
    uint32_t a;
    asm("{ .reg .u64 t; cvta.to.shared.u64 t, %1; cvt.u32.u64 %0, t; }" : "=r"(a) : "l"(p));
    return a;
}
#define LDSM_X4(r, addr) \
    asm volatile("ldmatrix.sync.aligned.m8n8.x4.shared.b16 {%0,%1,%2,%3}, [%4];" \
        : "=r"((r)[0]), "=r"((r)[1]), "=r"((r)[2]), "=r"((r)[3]) : "r"(addr))
#define MMA16816(d, a, b0, b1) \
    asm volatile("mma.sync.aligned.m16n8k16.row.col.f32.bf16.bf16.f32 " \
        "{%0,%1,%2,%3}, {%4,%5,%6,%7}, {%8,%9}, {%0,%1,%2,%3};" \
        : "+f"((d)[0]), "+f"((d)[1]), "+f"((d)[2]), "+f"((d)[3]) \
        : "r"((a)[0]), "r"((a)[1]), "r"((a)[2]), "r"((a)[3]), "r"(b0), "r"(b1))
#define CP_ASYNC16(dst, src) \
    asm volatile("cp.async.cg.shared.global [%0], [%1], 16;" :: "r"(dst), "l"(src))
#define CP_COMMIT() asm volatile("cp.async.commit_group;" ::: "memory")
#define CP_WAIT_1() asm volatile("cp.async.wait_group 1;" ::: "memory")
#define CP_WAIT_0() asm volatile("cp.async.wait_group 0;" ::: "memory")

// ---------------- device scratch ----------------
__device__ float         g_enorm[NCODES];
__device__ __nv_bfloat16 g_cbhi[NCODES * CDIM];
__device__ __nv_bfloat16 g_cblo[NCODES * CDIM];
__device__ float         g_zn[NPIX];
__device__ int           g_idx[NPIX];
__device__ int           g_flag[NPIX];
__device__ int           g_nflag;

extern __shared__ float smem[];

// ---------------- prep: enorm (exact chain) + codebook hi/lo split ----------------
__global__ void prep_kernel(const float* __restrict__ cb) {
    int gid = blockIdx.x * 256 + threadIdx.x;            // 262144 threads
    float v = cb[gid];
    __nv_bfloat16 h = __float2bfloat16_rn(v);
    float vh = __bfloat162float(h);
    __nv_bfloat16 l = __float2bfloat16_rn(__fsub_rn(v, vh));
    g_cbhi[gid] = h;
    g_cblo[gid] = l;
    if (gid < NCODES) {
        float acc = 0.f;
        const float* row = cb + gid * CDIM;
        for (int c = 0; c < CDIM; ++c) {
            float x = row[c];
            acc = __fadd_rn(acc, __fmul_rn(x, x));
        }
        g_enorm[gid] = acc;
    }
    if (gid == 0) g_nflag = 0;
}

// ---------------- main MMA kernel ----------------
// smem bytes:
//   A:   [0, 133120)      128 rows x 1040B  (512 bf16 = [zhi(256)|zlo(256)], 16B pad)
//   B:   [133120, 169984) 2 stages x (128 rows x 144B); also f32 staging (32KB)
//                         during A-build; also u64 T1/T2 tables (16KB) after mainloop
//   EN:  [169984, 174080) 1024 f32 codebook norms
//   ZNS: [174080, 174592) 128 f32 pixel norms
#define SB_A    0
#define SB_B    133120
#define SB_EN   169984
#define SB_ZNS  174080
#define SMEM_VQ 174592
#define A_PITCH 1040
#define B_PITCH 144
#define B_STAGE 18432

__device__ __forceinline__ void issue_chunk(uint32_t Bu, int cidx, int tid) {
    int nt = cidx >> 3, ch = cidx & 7;
    const __nv_bfloat16* src = (ch < 4) ? g_cbhi : g_cblo;
    int kc = (ch & 3) * 64;
    int r = tid >> 1;
    const char* gbase = (const char*)src + (size_t)(nt * 128 + r) * 512 + kc * 2;
    uint32_t dbase = Bu + r * B_PITCH;
    int s0 = (tid & 1) * 4;
    #pragma unroll
    for (int i = 0; i < 4; ++i)
        CP_ASYNC16(dbase + (s0 + i) * 16, gbase + (s0 + i) * 16);
    CP_COMMIT();
}

__device__ __forceinline__ void upd(unsigned long long key,
                                    unsigned long long& k1, unsigned long long& k2) {
    if (key < k1) { k2 = k1; k1 = key; }
    else if (key < k2) { k2 = key; }
}
__device__ __forceinline__ unsigned long long mkkey(float d, int code) {
    return ((unsigned long long)__float_as_uint(d) << 32) | (unsigned)code;
}

// 4 k-steps (one 64-K chunk) of the warp tile: A base col kA (elements), B stage base
__device__ __forceinline__ void mma_chunk(uint32_t arow, uint32_t brow, int kA,
                                          float acc[2][8][4]) {
    #pragma unroll
    for (int s = 0; s < 4; ++s) {
        uint32_t a[2][4];
        #pragma unroll
        for (int mi = 0; mi < 2; ++mi)
            LDSM_X4(a[mi], arow + mi * (16 * A_PITCH) + (kA + s * 16) * 2);
        uint32_t bf[4][4];
        #pragma unroll
        for (int nj = 0; nj < 4; ++nj)
            LDSM_X4(bf[nj], brow + nj * (16 * B_PITCH) + s * 32);
        #pragma unroll
        for (int mi = 0; mi < 2; ++mi)
            #pragma unroll
            for (int j = 0; j < 8; ++j)
                MMA16816(acc[mi][j], a[mi], bf[j >> 1][(j & 1) * 2], bf[j >> 1][(j & 1) * 2 + 1]);
    }
}

__global__ __launch_bounds__(256, 1)
void vq_mma_kernel(const float* __restrict__ z) {
    char* sc = (char*)smem;
    float* Astage = (float*)(sc + SB_B);       // f32 staging during A build
    float* en_s   = (float*)(sc + SB_EN);
    float* zns    = (float*)(sc + SB_ZNS);
    const uint32_t Au = smem_u32(sc + SB_A);
    const uint32_t Bu = smem_u32(sc + SB_B);

    const int tid  = threadIdx.x;
    const int wid  = tid >> 5;
    const int lane = tid & 31;
    const int g = lane >> 2, t = lane & 3;
    const int wm = wid & 3, wn = wid >> 2;

    const int pb = blockIdx.x;
    const int pix0 = pb * PIX_TILE;
    const int b = pb >> 5;
    const int o4 = ((pb & 31) * PIX_TILE) >> 2;
    const float4* zg4 = (const float4*)z + (size_t)b * (CDIM * HW / 4);

    // ---- preload codebook norms ----
    for (int j = tid; j < NCODES; j += 256) en_s[j] = g_enorm[j];

    // ---- build A = [zhi|zlo] bf16 rows + exact zn chains, 4 chunks of 64 c ----
    float znacc = 0.f;
    for (int q = 0; q < 4; ++q) {
        for (int j = tid; j < 64 * 32; j += 256) {       // 64 c x 128 p as float4
            int cl = j >> 5, v = j & 31;
            ((float4*)Astage)[cl * 32 + v] = zg4[(q * 64 + cl) * (HW / 4) + o4 + v];
        }
        __syncthreads();
        if (tid < 128) {
            char* arow = sc + SB_A + tid * A_PITCH;
            for (int cc = 0; cc < 64; cc += 2) {
                float v0 = Astage[cc * 128 + tid];
                float v1 = Astage[(cc + 1) * 128 + tid];
                znacc = __fadd_rn(znacc, __fmul_rn(v0, v0));
                znacc = __fadd_rn(znacc, __fmul_rn(v1, v1));
                __nv_bfloat16 h0 = __float2bfloat16_rn(v0), h1 = __float2bfloat16_rn(v1);
                float r0 = __fsub_rn(v0, __bfloat162float(h0));
                float r1 = __fsub_rn(v1, __bfloat162float(h1));
                __nv_bfloat16 l0 = __float2bfloat16_rn(r0), l1 = __float2bfloat16_rn(r1);
                uint32_t hp = ((uint32_t)__bfloat16_as_ushort(h1) << 16) | __bfloat16_as_ushort(h0);
                uint32_t lp = ((uint32_t)__bfloat16_as_ushort(l1) << 16) | __bfloat16_as_ushort(l0);
                *(uint32_t*)(arow + (q * 64 + cc) * 2)       = hp;
                *(uint32_t*)(arow + 512 + (q * 64 + cc) * 2) = lp;
            }
        }
        __syncthreads();
    }
    if (tid < 128) { zns[tid] = znacc; g_zn[pix0 + tid] = znacc; }
    __syncthreads();

    // ---- fragment base addresses ----
    const uint32_t arow = Au + (wm * 32 + (lane & 15)) * A_PITCH + (lane >> 4) * 16;
    const uint32_t brow0 = Bu + (wn * 64 + ((lane & 7) | ((lane & 16) >> 1))) * B_PITCH
                              + ((lane >> 3) & 1) * 16;
    float zn0[2], zn1[2];
    #pragma unroll
    for (int mi = 0; mi < 2; ++mi) {
        zn0[mi] = zns[wm * 32 + mi * 16 + g];
        zn1[mi] = zns[wm * 32 + mi * 16 + 8 + g];
    }

    unsigned long long K1[4], K2[4];
    #pragma unroll
    for (int s = 0; s < 4; ++s) { K1[s] = ~0ull; K2[s] = ~0ull; }

    float acc[2][8][4];

    // ---- mainloop: 8 N-tiles x 8 chunks, cp.async double buffered ----
    issue_chunk(Bu, 0, tid);
    for (int it = 0; it < 64; ++it) {
        const int nt = it >> 3, ch = it & 7;
        if (it + 1 < 64) { issue_chunk(Bu + ((it + 1) & 1) * B_STAGE, it + 1, tid); CP_WAIT_1(); }
        else             { CP_WAIT_0(); }
        __syncthreads();

        if (ch == 0) {
            #pragma unroll
            for (int mi = 0; mi < 2; ++mi)
                #pragma unroll
                for (int j = 0; j < 8; ++j)
                    #pragma unroll
                    for (int r = 0; r < 4; ++r) acc[mi][j][r] = 0.f;
        }

        const uint32_t brow = brow0 + (it & 1) * B_STAGE;
        if (ch < 4) {
            mma_chunk(arow, brow, ch * 64, acc);         // zhi . ehi
            mma_chunk(arow, brow, 256 + ch * 64, acc);   // zlo . ehi
        } else {
            mma_chunk(arow, brow, (ch - 4) * 64, acc);   // zhi . elo
        }

        if (ch == 7) {
            // epilogue: d = fl(fl(zn+en) - fl(2*dot)), running (min1,min2) u64 keys
            #pragma unroll
            for (int mi = 0; mi < 2; ++mi) {
                #pragma unroll
                for (int j = 0; j < 8; ++j) {
                    int cb0 = nt * 128 + wn * 64 + j * 8 + 2 * t;
                    float2 en2 = *(const float2*)(en_s + cb0);
                    float d0 = __fsub_rn(__fadd_rn(zn0[mi], en2.x), __fmul_rn(2.f, acc[mi][j][0]));
                    float d1 = __fsub_rn(__fadd_rn(zn0[mi], en2.y), __fmul_rn(2.f, acc[mi][j][1]));
                    float d2 = __fsub_rn(__fadd_rn(zn1[mi], en2.x), __fmul_rn(2.f, acc[mi][j][2]));
                    float d3 = __fsub_rn(__fadd_rn(zn1[mi], en2.y), __fmul_rn(2.f, acc[mi][j][3]));
                    upd(mkkey(d0, cb0),     K1[mi * 2],     K2[mi * 2]);
                    upd(mkkey(d1, cb0 + 1), K1[mi * 2],     K2[mi * 2]);
                    upd(mkkey(d2, cb0),     K1[mi * 2 + 1], K2[mi * 2 + 1]);
                    upd(mkkey(d3, cb0 + 1), K1[mi * 2 + 1], K2[mi * 2 + 1]);
                }
            }
        }
        __syncthreads();
    }

    // ---- cross-thread reduce: tables in B region ----
    unsigned long long* T1 = (unsigned long long*)(sc + SB_B);
    unsigned long long* T2 = T1 + 1024;
    #pragma unroll
    for (int mi = 0; mi < 2; ++mi)
        #pragma unroll
        for (int half = 0; half < 2; ++half) {
            int pixel = wm * 32 + mi * 16 + half * 8 + g;
            int e = wn * 4 + t;
            T1[pixel * 8 + e] = K1[mi * 2 + half];
            T2[pixel * 8 + e] = K2[mi * 2 + half];
        }
    __syncthreads();
    if (tid < 128) {
        unsigned long long g1 = ~0ull, g2 = ~0ull;
        #pragma unroll
        for (int e = 0; e < 8; ++e) {
            unsigned long long a = T1[tid * 8 + e], bb = T2[tid * 8 + e];
            if (a < g1) { g2 = g1; g1 = a; if (bb < g2) g2 = bb; }
            else if (a < g2) { g2 = a; }
        }
        int idx = (int)(g1 & 0xffffffffu);
        g_idx[pix0 + tid] = idx;
        float d1 = __uint_as_float((uint32_t)(g1 >> 32));
        float d2 = __uint_as_float((uint32_t)(g2 >> 32));
        if (d2 - d1 <= THRESH) {
            int pos = atomicAdd(&g_nflag, 1);
            g_flag[pos] = pix0 + tid;
        }
    }
}

// ---------------- exact fallback (R2-validated numerics) ----------------
#define FB_CBT   0
#define FB_ZR    65792
#define FB_TABV  (65792 + 16384)
#define FB_TABI  (FB_TABV + 2048)
#define FB_LIST  (FB_TABI + 2048)
#define FB_ZN    (FB_LIST + 64)
#define SMEM_FB  (FB_ZN + 64)

__global__ __launch_bounds__(256, 1)
void fallback_kernel(const float* __restrict__ z, const float* __restrict__ cb) {
    char* sc = (char*)smem;
    float* cbT  = (float*)(sc + FB_CBT);     // 64 x 257
    float* Zr   = (float*)(sc + FB_ZR);      // 16 x 256
    float* tabv = (float*)(sc + FB_TABV);
    int*   tabi = (int*)(sc + FB_TABI);
    int*   list = (int*)(sc + FB_LIST);
    float* znl  = (float*)(sc + FB_ZN);

    const int tid = threadIdx.x;
    const int w = tid >> 5, l = tid & 31;
    const int nf = g_nflag;
    const float4* cb4 = (const float4*)cb;

    for (int base = blockIdx.x * 16; base < nf; base += gridDim.x * 16) {
        int cnt = min(16, nf - base);
        if (tid < cnt) {
            int px = g_flag[base + tid];
            list[tid] = px;
            znl[tid] = g_zn[px];
        }
        __syncthreads();
        for (int j = tid; j < cnt * 256; j += 256) {
            int s = j >> 8, c = j & 255;
            int px = list[s];
            Zr[s * 256 + c] = z[(size_t)(px >> 12) * (CDIM * HW) + (size_t)c * HW + (px & 4095)];
        }
        __syncthreads();

        float mv[2] = {CUDART_INF_F, CUDART_INF_F};
        int   mi[2] = {0x7fffffff, 0x7fffffff};
        for (int kt = 0; kt < 16; ++kt) {
            for (int j = tid; j < 64 * 64; j += 256) {
                int r = j >> 6, v4 = j & 63;
                float4 e = cb4[(kt * 64 + r) * 64 + v4];
                float* dst = &cbT[r * 257 + v4 * 4];
                dst[0] = e.x; dst[1] = e.y; dst[2] = e.z; dst[3] = e.w;
            }
            __syncthreads();
            #pragma unroll
            for (int ss = 0; ss < 2; ++ss) {
                int s = w + ss * 8;
                if (s < cnt) {
                    float a0 = 0.f, a1 = 0.f;
                    const float* zr = &Zr[s * 256];
                    const float* c0 = &cbT[l * 257];
                    const float* c1 = &cbT[(l + 32) * 257];
                    for (int c = 0; c < 256; ++c) {
                        float zv = zr[c];
                        a0 = __fmaf_rn(zv, c0[c], a0);
                        a1 = __fmaf_rn(zv, c1[c], a1);
                    }
                    int k0 = kt * 64 + l, k1 = kt * 64 + l + 32;
                    float d0 = __fsub_rn(__fadd_rn(znl[s], g_enorm[k0]), __fmul_rn(2.0f, a0));
                    float d1 = __fsub_rn(__fadd_rn(znl[s], g_enorm[k1]), __fmul_rn(2.0f, a1));
                    if (d0 < mv[ss] || (d0 == mv[ss] && k0 < mi[ss])) { mv[ss] = d0; mi[ss] = k0; }
                    if (d1 < mv[ss] || (d1 == mv[ss] && k1 < mi[ss])) { mv[ss] = d1; mi[ss] = k1; }
                }
            }
            __syncthreads();
        }
        #pragma unroll
        for (int ss = 0; ss < 2; ++ss) {
            int s = w + ss * 8;
            if (s < 16) { tabv[s * 32 + l] = mv[ss]; tabi[s * 32 + l] = mi[ss]; }
        }
        __syncthreads();
        if (tid < cnt) {
            float bv = tabv[tid * 32];
            int bi = tabi[tid * 32];
            for (int i = 1; i < 32; ++i) {
                float v = tabv[tid * 32 + i];
                int x = tabi[tid * 32 + i];
                if (v < bv || (v == bv && x < bi)) { bv = v; bi = x; }
            }
            g_idx[list[tid]] = bi;
        }
        __syncthreads();
    }
}

// ---------------- output: gather + STE write (R2-validated tail) ----------------
#define OG_IDX 33792
#define SMEM_OUT ((33792 + 128) * 4)
__global__ __launch_bounds__(256, 1)
void output_kernel(const float* __restrict__ z, const float* __restrict__ cb,
                   float* __restrict__ out) {
    float* gbuf = smem;
    int* idxf = (int*)(smem + OG_IDX);
    const int tid = threadIdx.x;
    const int pb = blockIdx.x;
    const int b = pb >> 5;
    const int o4 = ((pb & 31) * PIX_TILE) >> 2;
    const float4* zg4 = (const float4*)z + (size_t)b * (CDIM * HW / 4);
    float4* out4 = (float4*)out + (size_t)b * (CDIM * HW / 4);
    const float4* cb4 = (const float4*)cb;

    if (tid < PIX_TILE) idxf[tid] = g_idx[pb * PIX_TILE + tid];
    __syncthreads();

    for (int j = tid; j < PIX_TILE * (CDIM / 4); j += 256) {
        int p = j >> 6, v = j & 63;
        float4 e = cb4[idxf[p] * (CDIM / 4) + v];
        int c = v * 4;
        gbuf[(c + 0) * 132 + p] = e.x;
        gbuf[(c + 1) * 132 + p] = e.y;
        gbuf[(c + 2) * 132 + p] = e.z;
        gbuf[(c + 3) * 132 + p] = e.w;
    }
    __syncthreads();

    for (int i = tid; i < CDIM * (PIX_TILE / 4); i += 256) {
        int c = i >> 5, v = i & 31;
        float4 q = *(const float4*)&gbuf[c * 132 + v * 4];
        float4 zv = zg4[c * (HW / 4) + o4 + v];
        float4 o;
        o.x = __fadd_rn(zv.x, __fsub_rn(q.x, zv.x));
        o.y = __fadd_rn(zv.y, __fsub_rn(q.y, zv.y));
        o.z = __fadd_rn(zv.z, __fsub_rn(q.z, zv.z));
        o.w = __fadd_rn(zv.w, __fsub_rn(q.w, zv.w));
        out4[c * (HW / 4) + o4 + v] = o;
    }
}

// ---------------- launch ----------------
extern "C" void kernel_launch(void* const* d_in, const int* in_sizes, int n_in,
                              void* d_out, int out_size) {
    const float* z  = (const float*)d_in[0];
    const float* cb = (const float*)d_in[1];
    float* out = (float*)d_out;

    cudaFuncSetAttribute(vq_mma_kernel, cudaFuncAttributeMaxDynamicSharedMemorySize, SMEM_VQ);
    cudaFuncSetAttribute(fallback_kernel, cudaFuncAttributeMaxDynamicSharedMemorySize, SMEM_FB);
    cudaFuncSetAttribute(output_kernel, cudaFuncAttributeMaxDynamicSharedMemorySize, SMEM_OUT);

    prep_kernel<<<NCODES * CDIM / 256, 256>>>(cb);
    vq_mma_kernel<<<NPIX / PIX_TILE, 256, SMEM_VQ>>>(z);
    fallback_kernel<<<512, 256, SMEM_FB>>>(z, cb);
    output_kernel<<<NPIX / PIX_TILE, 256, SMEM_OUT>>>(z, cb, out);
}

// round 6
// speedup vs baseline: 1.4277x; 1.1070x over previous
#include <cuda_runtime.h>
#include <cuda_fp16.h>
#include <math_constants.h>
#include <cstdint>

#define BATCH 32
#define CDIM 256
#define HW 4096
#define NCODES 1024
#define NPIX (BATCH * HW)
#define PIX_TILE 128
#define THRESH 1.25e-4f
#define INV4096 2.44140625e-4f

// ---------------- PTX helpers (baseline PTX only) ----------------
__device__ __forceinline__ uint32_t smem_u32(const void* p) {
    uint32_t a;
    asm("{ .reg .u64 t; cvta.to.shared.u64 t, %1; cvt.u32.u64 %0, t; }" : "=r"(a) : "l"(p));
    return a;
}
#define LDSM_X4(r, addr) \
    asm volatile("ldmatrix.sync.aligned.m8n8.x4.shared.b16 {%0,%1,%2,%3}, [%4];" \
        : "=r"((r)[0]), "=r"((r)[1]), "=r"((r)[2]), "=r"((r)[3]) : "r"(addr))
#define MMA16816(d, a, b0, b1) \
    asm volatile("mma.sync.aligned.m16n8k16.row.col.f32.f16.f16.f32 " \
        "{%0,%1,%2,%3}, {%4,%5,%6,%7}, {%8,%9}, {%0,%1,%2,%3};" \
        : "+f"((d)[0]), "+f"((d)[1]), "+f"((d)[2]), "+f"((d)[3]) \
        : "r"((a)[0]), "r"((a)[1]), "r"((a)[2]), "r"((a)[3]), "r"(b0), "r"(b1))
#define CP_ASYNC16(dst, src) \
    asm volatile("cp.async.cg.shared.global [%0], [%1], 16;" :: "r"(dst), "l"(src))
#define CP_COMMIT() asm volatile("cp.async.commit_group;" ::: "memory")
#define CP_WAIT_1() asm volatile("cp.async.wait_group 1;" ::: "memory")
#define CP_WAIT_0() asm volatile("cp.async.wait_group 0;" ::: "memory")

// ---------------- device scratch ----------------
__device__ float  g_enorm[NCODES];
__device__ __half g_cbhi[NCODES * CDIM];
__device__ __half g_cblo[NCODES * CDIM];     // (e - fp16(e)) * 4096, fp16
__device__ float  g_zn[NPIX];
__device__ int    g_flag[NPIX];
__device__ int    g_nflag;

extern __shared__ float smem[];

// ---------------- prep ----------------
__global__ void prep_kernel(const float* __restrict__ cb) {
    int gid = blockIdx.x * 256 + threadIdx.x;            // 262144 threads
    float v = cb[gid];
    __half h = __float2half_rn(v);
    float r = __fsub_rn(v, __half2float(h));
    g_cbhi[gid] = h;
    g_cblo[gid] = __float2half_rn(__fmul_rn(r, 4096.0f));
    if (gid < NCODES) {
        float acc = 0.f;
        const float* row = cb + gid * CDIM;
        for (int c = 0; c < CDIM; ++c) {
            float x = row[c];
            acc = __fadd_rn(acc, __fmul_rn(x, x));
        }
        g_enorm[gid] = acc;
    }
    if (gid == 0) g_nflag = 0;
}

// ---------------- main MMA kernel (512 threads) ----------------
// smem bytes:
//   A:   [0, 133120)          128 rows x 1040B (512 fp16 = [zhi|zlo], 16B pad)
//   B:   [133120, 188416)     3 stages x (128 rows x 144B); staging / tables reuse
//   EN:  [188416, 192512)     1024 f32
//   ZNS: [192512, 193024)     128 f32
#define SB_A    0
#define SB_B    133120
#define SB_T1   133120
#define SB_T2   (133120 + 16384)
#define SB_IDXF (133120 + 40960)
#define SB_EN   188416
#define SB_ZNS  192512
#define SMEM_VQ 193024
#define A_PITCH 1040
#define B_PITCH 144
#define B_STAGE 18432

__device__ __forceinline__ void issue_chunk(uint32_t Bs, int cidx, int tid) {
    int nt = cidx >> 3, ch = cidx & 7;
    const __half* src = (ch < 4) ? g_cbhi : g_cblo;
    int kc = (ch & 3) * 64;
    int r = tid >> 2;                                    // 0..127 code row
    const char* gbase = (const char*)src + (size_t)(nt * 128 + r) * 512 + kc * 2;
    uint32_t dbase = Bs + r * B_PITCH + (tid & 3) * 32;
    CP_ASYNC16(dbase,      gbase + (tid & 3) * 32);
    CP_ASYNC16(dbase + 16, gbase + (tid & 3) * 32 + 16);
    CP_COMMIT();
}

__device__ __forceinline__ void upd(unsigned long long key,
                                    unsigned long long& k1, unsigned long long& k2) {
    if (key < k1) { k2 = k1; k1 = key; }
    else if (key < k2) { k2 = key; }
}
__device__ __forceinline__ unsigned long long mkkey(float d, int code) {
    return ((unsigned long long)__float_as_uint(d) << 32) | (unsigned)code;
}

// one 64-K chunk of a 32x32 warp tile
__device__ __forceinline__ void mma_chunk(uint32_t arow, uint32_t brow, int kA,
                                          float acc[2][4][4]) {
    #pragma unroll
    for (int s = 0; s < 4; ++s) {
        uint32_t a[2][4];
        #pragma unroll
        for (int mi = 0; mi < 2; ++mi)
            LDSM_X4(a[mi], arow + mi * (16 * A_PITCH) + (kA + s * 16) * 2);
        uint32_t bf[2][4];
        #pragma unroll
        for (int nj = 0; nj < 2; ++nj)
            LDSM_X4(bf[nj], brow + nj * (16 * B_PITCH) + s * 32);
        #pragma unroll
        for (int mi = 0; mi < 2; ++mi)
            #pragma unroll
            for (int j = 0; j < 4; ++j)
                MMA16816(acc[mi][j], a[mi], bf[j >> 1][(j & 1) * 2], bf[j >> 1][(j & 1) * 2 + 1]);
    }
}

__global__ __launch_bounds__(512, 1)
void vq_mma_kernel(const float* __restrict__ z, const float* __restrict__ cb,
                   float* __restrict__ out) {
    char* sc = (char*)smem;
    float* Astage = (float*)(sc + SB_B);       // f32 staging during A build
    float* en_s   = (float*)(sc + SB_EN);
    float* zns    = (float*)(sc + SB_ZNS);
    const uint32_t Au = smem_u32(sc + SB_A);
    const uint32_t Bu = smem_u32(sc + SB_B);

    const int tid  = threadIdx.x;
    const int wid  = tid >> 5;
    const int lane = tid & 31;
    const int g = lane >> 2, t = lane & 3;
    const int wm = wid & 3, wn = wid >> 2;     // 4 x 4 warp grid

    const int pb = blockIdx.x;
    const int pix0 = pb * PIX_TILE;
    const int b = pb >> 5;
    const int o4 = ((pb & 31) * PIX_TILE) >> 2;
    const float4* zg4  = (const float4*)z   + (size_t)b * (CDIM * HW / 4);
    float4*       out4 = (float4*)out       + (size_t)b * (CDIM * HW / 4);
    const float4* cb4  = (const float4*)cb;

    for (int j = tid; j < NCODES; j += 512) en_s[j] = g_enorm[j];

    // ---- build A = [zhi|zlo] fp16 rows + exact zn chains ----
    float znacc = 0.f;
    for (int q = 0; q < 4; ++q) {
        for (int j = tid; j < 64 * 32; j += 512) {
            int cl = j >> 5, v = j & 31;
            ((float4*)Astage)[cl * 32 + v] = zg4[(q * 64 + cl) * (HW / 4) + o4 + v];
        }
        __syncthreads();
        if (tid < 128) {
            char* arow = sc + SB_A + tid * A_PITCH;
            for (int cc = 0; cc < 64; cc += 2) {
                float v0 = Astage[cc * 128 + tid];
                float v1 = Astage[(cc + 1) * 128 + tid];
                znacc = __fadd_rn(znacc, __fmul_rn(v0, v0));
                znacc = __fadd_rn(znacc, __fmul_rn(v1, v1));
                __half h0 = __float2half_rn(v0), h1 = __float2half_rn(v1);
                float r0 = __fsub_rn(v0, __half2float(h0));
                float r1 = __fsub_rn(v1, __half2float(h1));
                __half l0 = __float2half_rn(r0), l1 = __float2half_rn(r1);
                uint32_t hp = ((uint32_t)__half_as_ushort(h1) << 16) | __half_as_ushort(h0);
                uint32_t lp = ((uint32_t)__half_as_ushort(l1) << 16) | __half_as_ushort(l0);
                *(uint32_t*)(arow + (q * 64 + cc) * 2)       = hp;
                *(uint32_t*)(arow + 512 + (q * 64 + cc) * 2) = lp;
            }
        }
        __syncthreads();
    }
    if (tid < 128) { zns[tid] = znacc; g_zn[pix0 + tid] = znacc; }
    __syncthreads();

    // ---- fragment bases ----
    const uint32_t arow  = Au + (wm * 32 + (lane & 15)) * A_PITCH + (lane >> 4) * 16;
    const uint32_t brow0 = Bu + (wn * 32 + ((lane & 7) | ((lane & 16) >> 1))) * B_PITCH
                              + ((lane >> 3) & 1) * 16;
    float zn0[2], zn1[2];
    #pragma unroll
    for (int mi = 0; mi < 2; ++mi) {
        zn0[mi] = zns[wm * 32 + mi * 16 + g];
        zn1[mi] = zns[wm * 32 + mi * 16 + 8 + g];
    }

    unsigned long long K1[4], K2[4];
    #pragma unroll
    for (int s = 0; s < 4; ++s) { K1[s] = ~0ull; K2[s] = ~0ull; }

    float acc[2][4][4], accL[2][4][4];

    // ---- mainloop: 8 N-tiles x 8 chunks, 3-stage cp.async, 1 barrier/iter ----
    issue_chunk(Bu, 0, tid);
    issue_chunk(Bu + B_STAGE, 1, tid);
    for (int it = 0; it < 64; ++it) {
        const int nt = it >> 3, ch = it & 7;
        if (it < 63) CP_WAIT_1(); else CP_WAIT_0();
        __syncthreads();
        if (it + 2 < 64) issue_chunk(Bu + ((it + 2) % 3) * B_STAGE, it + 2, tid);

        if (ch == 0) {
            #pragma unroll
            for (int mi = 0; mi < 2; ++mi)
                #pragma unroll
                for (int j = 0; j < 4; ++j)
                    #pragma unroll
                    for (int r = 0; r < 4; ++r) { acc[mi][j][r] = 0.f; accL[mi][j][r] = 0.f; }
        }

        const uint32_t brow = brow0 + (it % 3) * B_STAGE;
        if (ch < 4) {
            mma_chunk(arow, brow, ch * 64, acc);         // zhi . ehi
            mma_chunk(arow, brow, 256 + ch * 64, acc);   // zlo . ehi
        } else {
            mma_chunk(arow, brow, (ch - 4) * 64, accL);  // zhi . (elo*4096)
        }

        if (ch == 7) {
            #pragma unroll
            for (int mi = 0; mi < 2; ++mi) {
                #pragma unroll
                for (int j = 0; j < 4; ++j) {
                    int cb0 = nt * 128 + wn * 32 + j * 8 + 2 * t;
                    float2 en2 = *(const float2*)(en_s + cb0);
                    float dt0 = __fmaf_rn(accL[mi][j][0], INV4096, acc[mi][j][0]);
                    float dt1 = __fmaf_rn(accL[mi][j][1], INV4096, acc[mi][j][1]);
                    float dt2 = __fmaf_rn(accL[mi][j][2], INV4096, acc[mi][j][2]);
                    float dt3 = __fmaf_rn(accL[mi][j][3], INV4096, acc[mi][j][3]);
                    float d0 = __fsub_rn(__fadd_rn(zn0[mi], en2.x), __fmul_rn(2.f, dt0));
                    float d1 = __fsub_rn(__fadd_rn(zn0[mi], en2.y), __fmul_rn(2.f, dt1));
                    float d2 = __fsub_rn(__fadd_rn(zn1[mi], en2.x), __fmul_rn(2.f, dt2));
                    float d3 = __fsub_rn(__fadd_rn(zn1[mi], en2.y), __fmul_rn(2.f, dt3));
                    upd(mkkey(d0, cb0),     K1[mi * 2],     K2[mi * 2]);
                    upd(mkkey(d1, cb0 + 1), K1[mi * 2],     K2[mi * 2]);
                    upd(mkkey(d2, cb0),     K1[mi * 2 + 1], K2[mi * 2 + 1]);
                    upd(mkkey(d3, cb0 + 1), K1[mi * 2 + 1], K2[mi * 2 + 1]);
                }
            }
        }
    }
    __syncthreads();

    // ---- cross-thread reduce (16 partials per pixel) ----
    unsigned long long* T1 = (unsigned long long*)(sc + SB_T1);
    unsigned long long* T2 = (unsigned long long*)(sc + SB_T2);
    int* idxf = (int*)(sc + SB_IDXF);
    #pragma unroll
    for (int mi = 0; mi < 2; ++mi)
        #pragma unroll
        for (int half = 0; half < 2; ++half) {
            int pixel = wm * 32 + mi * 16 + half * 8 + g;
            int e = wn * 4 + t;
            T1[pixel * 16 + e] = K1[mi * 2 + half];
            T2[pixel * 16 + e] = K2[mi * 2 + half];
        }
    __syncthreads();
    if (tid < 128) {
        unsigned long long g1 = ~0ull, g2 = ~0ull;
        #pragma unroll
        for (int e = 0; e < 16; ++e) {
            unsigned long long a = T1[tid * 16 + e], bb = T2[tid * 16 + e];
            if (a < g1) { g2 = g1; g1 = a; if (bb < g2) g2 = bb; }
            else if (a < g2) { g2 = a; }
        }
        idxf[tid] = (int)(g1 & 0xffffffffu);
        float d1 = __uint_as_float((uint32_t)(g1 >> 32));
        float d2 = __uint_as_float((uint32_t)(g2 >> 32));
        if (d2 - d1 <= THRESH) {
            int pos = atomicAdd(&g_nflag, 1);
            g_flag[pos] = pix0 + tid;
        }
    }
    __syncthreads();

    // ---- fused output: gather + STE write ----
    float* gbuf = (float*)sc;                   // pitch 132, overlaps dead A/B
    for (int j = tid; j < PIX_TILE * (CDIM / 4); j += 512) {
        int p = j >> 6, v = j & 63;
        float4 e = cb4[idxf[p] * (CDIM / 4) + v];
        int c = v * 4;
        gbuf[(c + 0) * 132 + p] = e.x;
        gbuf[(c + 1) * 132 + p] = e.y;
        gbuf[(c + 2) * 132 + p] = e.z;
        gbuf[(c + 3) * 132 + p] = e.w;
    }
    __syncthreads();
    for (int i = tid; i < CDIM * (PIX_TILE / 4); i += 512) {
        int c = i >> 5, v = i & 31;
        float4 q = *(const float4*)&gbuf[c * 132 + v * 4];
        float4 zv = zg4[c * (HW / 4) + o4 + v];
        float4 o;
        o.x = __fadd_rn(zv.x, __fsub_rn(q.x, zv.x));
        o.y = __fadd_rn(zv.y, __fsub_rn(q.y, zv.y));
        o.z = __fadd_rn(zv.z, __fsub_rn(q.z, zv.z));
        o.w = __fadd_rn(zv.w, __fsub_rn(q.w, zv.w));
        out4[c * (HW / 4) + o4 + v] = o;
    }
}

// ---------------- exact fallback (R2-validated numerics) + output rewrite ----
#define FB_CBT   0
#define FB_ZR    65792
#define FB_TABV  (65792 + 16384)
#define FB_TABI  (FB_TABV + 2048)
#define FB_LIST  (FB_TABI + 2048)
#define FB_ZN    (FB_LIST + 64)
#define FB_FIDX  (FB_ZN + 64)
#define SMEM_FB  (FB_FIDX + 64)

__global__ __launch_bounds__(256, 1)
void fallback_kernel(const float* __restrict__ z, const float* __restrict__ cb,
                     float* __restrict__ out) {
    char* sc = (char*)smem;
    float* cbT  = (float*)(sc + FB_CBT);     // 64 x 257
    float* Zr   = (float*)(sc + FB_ZR);      // 16 x 256
    float* tabv = (float*)(sc + FB_TABV);
    int*   tabi = (int*)(sc + FB_TABI);
    int*   list = (int*)(sc + FB_LIST);
    float* znl  = (float*)(sc + FB_ZN);
    int*   fidx = (int*)(sc + FB_FIDX);

    const int tid = threadIdx.x;
    const int w = tid >> 5, l = tid & 31;
    const int nf = g_nflag;
    const float4* cb4 = (const float4*)cb;

    for (int base = blockIdx.x * 16; base < nf; base += gridDim.x * 16) {
        int cnt = min(16, nf - base);
        if (tid < cnt) {
            int px = g_flag[base + tid];
            list[tid] = px;
            znl[tid] = g_zn[px];
        }
        __syncthreads();
        for (int j = tid; j < cnt * 256; j += 256) {
            int s = j >> 8, c = j & 255;
            int px = list[s];
            Zr[s * 256 + c] = z[(size_t)(px >> 12) * (CDIM * HW) + (size_t)c * HW + (px & 4095)];
        }
        __syncthreads();

        float mv[2] = {CUDART_INF_F, CUDART_INF_F};
        int   mi[2] = {0x7fffffff, 0x7fffffff};
        for (int kt = 0; kt < 16; ++kt) {
            for (int j = tid; j < 64 * 64; j += 256) {
                int r = j >> 6, v4 = j & 63;
                float4 e = cb4[(kt * 64 + r) * 64 + v4];
                float* dst = &cbT[r * 257 + v4 * 4];
                dst[0] = e.x; dst[1] = e.y; dst[2] = e.z; dst[3] = e.w;
            }
            __syncthreads();
            #pragma unroll
            for (int ss = 0; ss < 2; ++ss) {
                int s = w + ss * 8;
                if (s < cnt) {
                    float a0 = 0.f, a1 = 0.f;
                    const float* zr = &Zr[s * 256];
                    const float* c0 = &cbT[l * 257];
                    const float* c1 = &cbT[(l + 32) * 257];
                    for (int c = 0; c < 256; ++c) {
                        float zv = zr[c];
                        a0 = __fmaf_rn(zv, c0[c], a0);
                        a1 = __fmaf_rn(zv, c1[c], a1);
                    }
                    int k0 = kt * 64 + l, k1 = kt * 64 + l + 32;
                    float d0 = __fsub_rn(__fadd_rn(znl[s], g_enorm[k0]), __fmul_rn(2.0f, a0));
                    float d1 = __fsub_rn(__fadd_rn(znl[s], g_enorm[k1]), __fmul_rn(2.0f, a1));
                    if (d0 < mv[ss] || (d0 == mv[ss] && k0 < mi[ss])) { mv[ss] = d0; mi[ss] = k0; }
                    if (d1 < mv[ss] || (d1 == mv[ss] && k1 < mi[ss])) { mv[ss] = d1; mi[ss] = k1; }
                }
            }
            __syncthreads();
        }
        #pragma unroll
        for (int ss = 0; ss < 2; ++ss) {
            int s = w + ss * 8;
            if (s < 16) { tabv[s * 32 + l] = mv[ss]; tabi[s * 32 + l] = mi[ss]; }
        }
        __syncthreads();
        if (tid < cnt) {
            float bv = tabv[tid * 32];
            int bi = tabi[tid * 32];
            for (int i = 1; i < 32; ++i) {
                float v = tabv[tid * 32 + i];
                int x = tabi[tid * 32 + i];
                if (v < bv || (v == bv && x < bi)) { bv = v; bi = x; }
            }
            fidx[tid] = bi;
        }
        __syncthreads();
        // rewrite output rows for these pixels with the exact index
        for (int j = tid; j < cnt * 256; j += 256) {
            int s = j >> 8, c = j & 255;
            int px = list[s];
            float zv = Zr[s * 256 + c];
            float e = cb[fidx[s] * CDIM + c];
            out[(size_t)(px >> 12) * (CDIM * HW) + (size_t)c * HW + (px & 4095)] =
                __fadd_rn(zv, __fsub_rn(e, zv));
        }
        __syncthreads();
    }
}

// ---------------- launch ----------------
extern "C" void kernel_launch(void* const* d_in, const int* in_sizes, int n_in,
                              void* d_out, int out_size) {
    const float* z  = (const float*)d_in[0];
    const float* cb = (const float*)d_in[1];
    float* out = (float*)d_out;

    cudaFuncSetAttribute(vq_mma_kernel, cudaFuncAttributeMaxDynamicSharedMemorySize, SMEM_VQ);
    cudaFuncSetAttribute(fallback_kernel, cudaFuncAttributeMaxDynamicSharedMemorySize, SMEM_FB);

    prep_kernel<<<NCODES * CDIM / 256, 256>>>(cb);
    vq_mma_kernel<<<NPIX / PIX_TILE, 512, SMEM_VQ>>>(z, cb, out);
    fallback_kernel<<<512, 256, SMEM_FB>>>(z, cb, out);
}

// round 7
// speedup vs baseline: 1.4606x; 1.0231x over previous
#include <cuda_runtime.h>
#include <cuda_fp16.h>
#include <math_constants.h>
#include <cstdint>

#define BATCH 32
#define CDIM 256
#define HW 4096
#define NCODES 1024
#define NPIX (BATCH * HW)
#define PIX_TILE 128
#define THRESH 1.25e-4f
#define INV4096 2.44140625e-4f

// ---------------- PTX helpers (baseline PTX only) ----------------
__device__ __forceinline__ uint32_t smem_u32(const void* p) {
    uint32_t a;
    asm("{ .reg .u64 t; cvta.to.shared.u64 t, %1; cvt.u32.u64 %0, t; }" : "=r"(a) : "l"(p));
    return a;
}
#define LDSM_X4(r, addr) \
    asm volatile("ldmatrix.sync.aligned.m8n8.x4.shared.b16 {%0,%1,%2,%3}, [%4];" \
        : "=r"((r)[0]), "=r"((r)[1]), "=r"((r)[2]), "=r"((r)[3]) : "r"(addr))
#define MMA16816(d, a, b0, b1) \
    asm volatile("mma.sync.aligned.m16n8k16.row.col.f32.f16.f16.f32 " \
        "{%0,%1,%2,%3}, {%4,%5,%6,%7}, {%8,%9}, {%0,%1,%2,%3};" \
        : "+f"((d)[0]), "+f"((d)[1]), "+f"((d)[2]), "+f"((d)[3]) \
        : "r"((a)[0]), "r"((a)[1]), "r"((a)[2]), "r"((a)[3]), "r"(b0), "r"(b1))
#define CP_ASYNC16(dst, src) \
    asm volatile("cp.async.cg.shared.global [%0], [%1], 16;" :: "r"(dst), "l"(src))
#define CP_COMMIT() asm volatile("cp.async.commit_group;" ::: "memory")
#define CP_WAIT_1() asm volatile("cp.async.wait_group 1;" ::: "memory")
#define CP_WAIT_0() asm volatile("cp.async.wait_group 0;" ::: "memory")

// ---------------- device scratch ----------------
__device__ float  g_enorm[NCODES];
__device__ __half g_cbhi[NCODES * CDIM];
__device__ __half g_cblo[NCODES * CDIM];     // (e - fp16(e)) * 4096, fp16
__device__ float  g_zn[NPIX];
__device__ int    g_flag[NPIX];
__device__ int    g_nflag;
__device__ int    g_pairA[NPIX];
__device__ int    g_pairB[NPIX];
__device__ int    g_npair;

extern __shared__ float smem[];

// ---------------- prep ----------------
__global__ void prep_kernel(const float* __restrict__ cb) {
    int gid = blockIdx.x * 256 + threadIdx.x;            // 262144 threads
    float v = cb[gid];
    __half h = __float2half_rn(v);
    float r = __fsub_rn(v, __half2float(h));
    g_cbhi[gid] = h;
    g_cblo[gid] = __float2half_rn(__fmul_rn(r, 4096.0f));
    if (gid < NCODES) {
        const float4* r4 = (const float4*)(cb + gid * CDIM);
        float acc = 0.f;
        #pragma unroll 8
        for (int c4 = 0; c4 < 64; ++c4) {
            float4 w = r4[c4];
            acc = __fadd_rn(acc, __fmul_rn(w.x, w.x));
            acc = __fadd_rn(acc, __fmul_rn(w.y, w.y));
            acc = __fadd_rn(acc, __fmul_rn(w.z, w.z));
            acc = __fadd_rn(acc, __fmul_rn(w.w, w.w));
        }
        g_enorm[gid] = acc;
    }
    if (gid == 0) { g_nflag = 0; g_npair = 0; }
}

// ---------------- main MMA kernel (512 threads) ----------------
// smem bytes:
//   A:   [0, 133120)          128 rows x 1040B (512 fp16 = [zhi|zlo], 16B pad)
//   B:   [133120, 206848)     2 stages x 36864 (hi 128x144 @0, lo @18432)
//        reused for: Astage (32KB), then T1/T2/T3/idxf tables, then gbuf overlap
//   EN:  [206848, 210944)     1024 f32
//   ZNS: [210944, 211456)     128 f32
#define SB_A    0
#define SB_B    133120
#define SB_T1   133120
#define SB_T2   (133120 + 16384)
#define SB_T3   (133120 + 32768)
#define SB_IDXF (133120 + 40960)
#define SB_EN   206848
#define SB_ZNS  210944
#define SMEM_VQ 211456
#define A_PITCH 1040
#define B_PITCH 144
#define B_STAGE 36864
#define B_LO    18432

__device__ __forceinline__ void issue_chunk(uint32_t Bs, int it, int tid) {
    int nt = it >> 2, kc = it & 3;
    int r = tid >> 2, q = tid & 3;                       // row 0..127, quarter
    size_t goff = (size_t)(nt * 128 + r) * 512 + kc * 128 + q * 32;
    uint32_t dst = Bs + r * B_PITCH + q * 32;
    const char* ghi = (const char*)g_cbhi + goff;
    const char* glo = (const char*)g_cblo + goff;
    CP_ASYNC16(dst,             ghi);
    CP_ASYNC16(dst + 16,        ghi + 16);
    CP_ASYNC16(dst + B_LO,      glo);
    CP_ASYNC16(dst + B_LO + 16, glo + 16);
    CP_COMMIT();
}

__device__ __forceinline__ float keyval(unsigned long long k) {
    return __uint_as_float((uint32_t)(k >> 32));
}
__device__ __forceinline__ unsigned long long mkkey(float d, int code) {
    return ((unsigned long long)__float_as_uint(d) << 32) | (unsigned)code;
}
__device__ __forceinline__ void upd3(unsigned long long key,
                                     unsigned long long& k1, unsigned long long& k2,
                                     float& m3) {
    if (key < k1)      { m3 = keyval(k2); k2 = k1; k1 = key; }
    else if (key < k2) { m3 = keyval(k2); k2 = key; }
    else { float v = keyval(key); if (v < m3) m3 = v; }
}

__global__ __launch_bounds__(512, 1)
void vq_mma_kernel(const float* __restrict__ z, const float* __restrict__ cb,
                   float* __restrict__ out) {
    char* sc = (char*)smem;
    float* Astage = (float*)(sc + SB_B);       // f32 staging during A build
    float* en_s   = (float*)(sc + SB_EN);
    float* zns    = (float*)(sc + SB_ZNS);
    const uint32_t Au = smem_u32(sc + SB_A);
    const uint32_t Bu = smem_u32(sc + SB_B);

    const int tid  = threadIdx.x;
    const int wid  = tid >> 5;
    const int lane = tid & 31;
    const int g = lane >> 2, t = lane & 3;
    const int wm = wid & 3, wn = wid >> 2;     // 4 x 4 warp grid

    const int pb = blockIdx.x;
    const int pix0 = pb * PIX_TILE;
    const int b = pb >> 5;
    const int o4 = ((pb & 31) * PIX_TILE) >> 2;
    const float4* zg4  = (const float4*)z   + (size_t)b * (CDIM * HW / 4);
    float4*       out4 = (float4*)out       + (size_t)b * (CDIM * HW / 4);
    const float4* cb4  = (const float4*)cb;

    for (int j = tid; j < NCODES; j += 512) en_s[j] = g_enorm[j];

    // ---- build A = [zhi|zlo] fp16 rows + exact zn chains ----
    float znacc = 0.f;
    for (int q = 0; q < 4; ++q) {
        for (int j = tid; j < 64 * 32; j += 512) {
            int cl = j >> 5, v = j & 31;
            ((float4*)Astage)[cl * 32 + v] = zg4[(q * 64 + cl) * (HW / 4) + o4 + v];
        }
        __syncthreads();
        if (tid < 128) {
            char* arow = sc + SB_A + tid * A_PITCH;
            for (int cc = 0; cc < 64; cc += 2) {
                float v0 = Astage[cc * 128 + tid];
                float v1 = Astage[(cc + 1) * 128 + tid];
                znacc = __fadd_rn(znacc, __fmul_rn(v0, v0));
                znacc = __fadd_rn(znacc, __fmul_rn(v1, v1));
                __half h0 = __float2half_rn(v0), h1 = __float2half_rn(v1);
                float r0 = __fsub_rn(v0, __half2float(h0));
                float r1 = __fsub_rn(v1, __half2float(h1));
                __half l0 = __float2half_rn(r0), l1 = __float2half_rn(r1);
                uint32_t hp = ((uint32_t)__half_as_ushort(h1) << 16) | __half_as_ushort(h0);
                uint32_t lp = ((uint32_t)__half_as_ushort(l1) << 16) | __half_as_ushort(l0);
                *(uint32_t*)(arow + (q * 64 + cc) * 2)       = hp;
                *(uint32_t*)(arow + 512 + (q * 64 + cc) * 2) = lp;
            }
        }
        __syncthreads();
    }
    if (tid < 128) { zns[tid] = znacc; g_zn[pix0 + tid] = znacc; }
    __syncthreads();

    // ---- fragment bases ----
    const uint32_t arow  = Au + (wm * 32 + (lane & 15)) * A_PITCH + (lane >> 4) * 16;
    const uint32_t brow0 = Bu + (wn * 32 + ((lane & 7) | ((lane & 16) >> 1))) * B_PITCH
                              + ((lane >> 3) & 1) * 16;
    float zn0[2], zn1[2];
    #pragma unroll
    for (int mi = 0; mi < 2; ++mi) {
        zn0[mi] = zns[wm * 32 + mi * 16 + g];
        zn1[mi] = zns[wm * 32 + mi * 16 + 8 + g];
    }

    unsigned long long K1[4], K2[4];
    float M3[4];
    #pragma unroll
    for (int s = 0; s < 4; ++s) { K1[s] = ~0ull; K2[s] = ~0ull; M3[s] = CUDART_INF_F; }

    float acc[2][4][4], accL[2][4][4];

    // ---- mainloop: 8 N-tiles x 4 K-chunks, unified 3-product pass ----
    issue_chunk(Bu, 0, tid);
    for (int it = 0; it < 32; ++it) {
        const int nt = it >> 2, kc = it & 3;
        if (it + 1 < 32) { issue_chunk(Bu + ((it + 1) & 1) * B_STAGE, it + 1, tid); CP_WAIT_1(); }
        else             { CP_WAIT_0(); }
        __syncthreads();

        if (kc == 0) {
            #pragma unroll
            for (int mi = 0; mi < 2; ++mi)
                #pragma unroll
                for (int j = 0; j < 4; ++j)
                    #pragma unroll
                    for (int r = 0; r < 4; ++r) { acc[mi][j][r] = 0.f; accL[mi][j][r] = 0.f; }
        }

        const uint32_t brow = brow0 + (it & 1) * B_STAGE;
        #pragma unroll
        for (int s = 0; s < 4; ++s) {
            const int kb = (kc * 64 + s * 16) * 2;
            uint32_t ahi[2][4], alo[2][4], bhi[2][4];
            #pragma unroll
            for (int mi = 0; mi < 2; ++mi)
                LDSM_X4(ahi[mi], arow + mi * (16 * A_PITCH) + kb);
            #pragma unroll
            for (int mi = 0; mi < 2; ++mi)
                LDSM_X4(alo[mi], arow + mi * (16 * A_PITCH) + 512 + kb);
            #pragma unroll
            for (int nj = 0; nj < 2; ++nj)
                LDSM_X4(bhi[nj], brow + nj * (16 * B_PITCH) + s * 32);
            #pragma unroll
            for (int mi = 0; mi < 2; ++mi)
                #pragma unroll
                for (int j = 0; j < 4; ++j)
                    MMA16816(acc[mi][j], ahi[mi], bhi[j >> 1][(j & 1) * 2], bhi[j >> 1][(j & 1) * 2 + 1]);
            #pragma unroll
            for (int mi = 0; mi < 2; ++mi)
                #pragma unroll
                for (int j = 0; j < 4; ++j)
                    MMA16816(acc[mi][j], alo[mi], bhi[j >> 1][(j & 1) * 2], bhi[j >> 1][(j & 1) * 2 + 1]);
            uint32_t blo[2][4];
            #pragma unroll
            for (int nj = 0; nj < 2; ++nj)
                LDSM_X4(blo[nj], brow + B_LO + nj * (16 * B_PITCH) + s * 32);
            #pragma unroll
            for (int mi = 0; mi < 2; ++mi)
                #pragma unroll
                for (int j = 0; j < 4; ++j)
                    MMA16816(accL[mi][j], ahi[mi], blo[j >> 1][(j & 1) * 2], blo[j >> 1][(j & 1) * 2 + 1]);
        }

        if (kc == 3) {
            #pragma unroll
            for (int mi = 0; mi < 2; ++mi) {
                #pragma unroll
                for (int j = 0; j < 4; ++j) {
                    int cb0 = nt * 128 + wn * 32 + j * 8 + 2 * t;
                    float2 en2 = *(const float2*)(en_s + cb0);
                    float dt0 = __fmaf_rn(accL[mi][j][0], INV4096, acc[mi][j][0]);
                    float dt1 = __fmaf_rn(accL[mi][j][1], INV4096, acc[mi][j][1]);
                    float dt2 = __fmaf_rn(accL[mi][j][2], INV4096, acc[mi][j][2]);
                    float dt3 = __fmaf_rn(accL[mi][j][3], INV4096, acc[mi][j][3]);
                    float d0 = __fsub_rn(__fadd_rn(zn0[mi], en2.x), __fmul_rn(2.f, dt0));
                    float d1 = __fsub_rn(__fadd_rn(zn0[mi], en2.y), __fmul_rn(2.f, dt1));
                    float d2 = __fsub_rn(__fadd_rn(zn1[mi], en2.x), __fmul_rn(2.f, dt2));
                    float d3 = __fsub_rn(__fadd_rn(zn1[mi], en2.y), __fmul_rn(2.f, dt3));
                    upd3(mkkey(d0, cb0),     K1[mi * 2],     K2[mi * 2],     M3[mi * 2]);
                    upd3(mkkey(d1, cb0 + 1), K1[mi * 2],     K2[mi * 2],     M3[mi * 2]);
                    upd3(mkkey(d2, cb0),     K1[mi * 2 + 1], K2[mi * 2 + 1], M3[mi * 2 + 1]);
                    upd3(mkkey(d3, cb0 + 1), K1[mi * 2 + 1], K2[mi * 2 + 1], M3[mi * 2 + 1]);
                }
            }
        }
        __syncthreads();
    }

    // ---- cross-thread reduce (16 partials per pixel), global top-3 ----
    unsigned long long* T1 = (unsigned long long*)(sc + SB_T1);
    unsigned long long* T2 = (unsigned long long*)(sc + SB_T2);
    float* T3 = (float*)(sc + SB_T3);
    int* idxf = (int*)(sc + SB_IDXF);
    #pragma unroll
    for (int mi = 0; mi < 2; ++mi)
        #pragma unroll
        for (int half = 0; half < 2; ++half) {
            int pixel = wm * 32 + mi * 16 + half * 8 + g;
            int e = wn * 4 + t;
            T1[pixel * 16 + e] = K1[mi * 2 + half];
            T2[pixel * 16 + e] = K2[mi * 2 + half];
            T3[pixel * 16 + e] = M3[mi * 2 + half];
        }
    __syncthreads();
    if (tid < 128) {
        unsigned long long g1 = ~0ull, g2 = ~0ull;
        float gm3 = CUDART_INF_F;
        #pragma unroll
        for (int e = 0; e < 16; ++e) {
            unsigned long long a = T1[tid * 16 + e], bb = T2[tid * 16 + e];
            float c3 = T3[tid * 16 + e];
            upd3(a, g1, g2, gm3);
            upd3(bb, g1, g2, gm3);
            gm3 = fminf(gm3, c3);
        }
        int i1 = (int)(g1 & 0xffffffffu);
        idxf[tid] = i1;
        float d1 = keyval(g1), d2 = keyval(g2);
        if (gm3 - d1 <= THRESH) {
            int pos = atomicAdd(&g_nflag, 1);
            g_flag[pos] = pix0 + tid;
        } else if (d2 - d1 <= THRESH) {
            int pos = atomicAdd(&g_npair, 1);
            g_pairA[pos] = pix0 + tid;
            g_pairB[pos] = i1 | ((int)(g2 & 0xffffffffu) << 16);
        }
    }
    __syncthreads();

    // ---- fused output: gather + STE write ----
    float* gbuf = (float*)sc;                   // pitch 132; overlaps dead A / T1-head
    for (int j = tid; j < PIX_TILE * (CDIM / 4); j += 512) {
        int p = j >> 6, v = j & 63;
        float4 e = cb4[idxf[p] * (CDIM / 4) + v];
        int c = v * 4;
        gbuf[(c + 0) * 132 + p] = e.x;
        gbuf[(c + 1) * 132 + p] = e.y;
        gbuf[(c + 2) * 132 + p] = e.z;
        gbuf[(c + 3) * 132 + p] = e.w;
    }
    __syncthreads();
    for (int i = tid; i < CDIM * (PIX_TILE / 4); i += 512) {
        int c = i >> 5, v = i & 31;
        float4 q = *(const float4*)&gbuf[c * 132 + v * 4];
        float4 zv = zg4[c * (HW / 4) + o4 + v];
        float4 o;
        o.x = __fadd_rn(zv.x, __fsub_rn(q.x, zv.x));
        o.y = __fadd_rn(zv.y, __fsub_rn(q.y, zv.y));
        o.z = __fadd_rn(zv.z, __fsub_rn(q.z, zv.z));
        o.w = __fadd_rn(zv.w, __fsub_rn(q.w, zv.w));
        out4[c * (HW / 4) + o4 + v] = o;
    }
}

// ---------------- pairwise exact resolve (Eigen-chain numerics) ----------------
__global__ __launch_bounds__(256, 4)
void pair_kernel(const float* __restrict__ z, const float* __restrict__ cb,
                 float* __restrict__ out) {
    const int n = g_npair;
    for (int i = blockIdx.x * blockDim.x + threadIdx.x; i < n;
         i += gridDim.x * blockDim.x) {
        int px = g_pairA[i], pk = g_pairB[i];
        int i1 = pk & 0xffff, i2 = (pk >> 16) & 0xffff;
        const float* zp = z + (size_t)(px >> 12) * (CDIM * HW) + (px & 4095);
        const float* c1 = cb + i1 * CDIM;
        const float* c2 = cb + i2 * CDIM;
        float a1 = 0.f, a2 = 0.f;
        #pragma unroll 8
        for (int c = 0; c < CDIM; ++c) {
            float zv = zp[(size_t)c * HW];
            a1 = __fmaf_rn(zv, c1[c], a1);
            a2 = __fmaf_rn(zv, c2[c], a2);
        }
        float zn = g_zn[px];
        float d1 = __fsub_rn(__fadd_rn(zn, g_enorm[i1]), __fmul_rn(2.f, a1));
        float d2 = __fsub_rn(__fadd_rn(zn, g_enorm[i2]), __fmul_rn(2.f, a2));
        int win = (d2 < d1 || (d2 == d1 && i2 < i1)) ? i2 : i1;
        if (win != i1) {
            const float* cw = cb + win * CDIM;
            float* op = out + (size_t)(px >> 12) * (CDIM * HW) + (px & 4095);
            #pragma unroll 8
            for (int c = 0; c < CDIM; ++c) {
                float zv = zp[(size_t)c * HW];
                op[(size_t)c * HW] = __fadd_rn(zv, __fsub_rn(cw[c], zv));
            }
        }
    }
}

// ---------------- rare full exact fallback (R2-validated numerics) ----------------
#define FB_CBT   0
#define FB_ZR    65792
#define FB_TABV  (65792 + 16384)
#define FB_TABI  (FB_TABV + 2048)
#define FB_LIST  (FB_TABI + 2048)
#define FB_ZN    (FB_LIST + 64)
#define FB_FIDX  (FB_ZN + 64)
#define SMEM_FB  (FB_FIDX + 64)

__global__ __launch_bounds__(256, 1)
void fallback_kernel(const float* __restrict__ z, const float* __restrict__ cb,
                     float* __restrict__ out) {
    char* sc = (char*)smem;
    float* cbT  = (float*)(sc + FB_CBT);     // 64 x 257
    float* Zr   = (float*)(sc + FB_ZR);      // 16 x 256
    float* tabv = (float*)(sc + FB_TABV);
    int*   tabi = (int*)(sc + FB_TABI);
    int*   list = (int*)(sc + FB_LIST);
    float* znl  = (float*)(sc + FB_ZN);
    int*   fidx = (int*)(sc + FB_FIDX);

    const int tid = threadIdx.x;
    const int w = tid >> 5, l = tid & 31;
    const int nf = g_nflag;
    const float4* cb4 = (const float4*)cb;

    for (int base = blockIdx.x * 16; base < nf; base += gridDim.x * 16) {
        int cnt = min(16, nf - base);
        if (tid < cnt) {
            int px = g_flag[base + tid];
            list[tid] = px;
            znl[tid] = g_zn[px];
        }
        __syncthreads();
        for (int j = tid; j < cnt * 256; j += 256) {
            int s = j >> 8, c = j & 255;
            int px = list[s];
            Zr[s * 256 + c] = z[(size_t)(px >> 12) * (CDIM * HW) + (size_t)c * HW + (px & 4095)];
        }
        __syncthreads();

        float mv[2] = {CUDART_INF_F, CUDART_INF_F};
        int   mi[2] = {0x7fffffff, 0x7fffffff};
        for (int kt = 0; kt < 16; ++kt) {
            for (int j = tid; j < 64 * 64; j += 256) {
                int r = j >> 6, v4 = j & 63;
                float4 e = cb4[(kt * 64 + r) * 64 + v4];
                float* dst = &cbT[r * 257 + v4 * 4];
                dst[0] = e.x; dst[1] = e.y; dst[2] = e.z; dst[3] = e.w;
            }
            __syncthreads();
            #pragma unroll
            for (int ss = 0; ss < 2; ++ss) {
                int s = w + ss * 8;
                if (s < cnt) {
                    float a0 = 0.f, a1 = 0.f;
                    const float* zr = &Zr[s * 256];
                    const float* c0 = &cbT[l * 257];
                    const float* c1 = &cbT[(l + 32) * 257];
                    for (int c = 0; c < 256; ++c) {
                        float zv = zr[c];
                        a0 = __fmaf_rn(zv, c0[c], a0);
                        a1 = __fmaf_rn(zv, c1[c], a1);
                    }
                    int k0 = kt * 64 + l, k1 = kt * 64 + l + 32;
                    float d0 = __fsub_rn(__fadd_rn(znl[s], g_enorm[k0]), __fmul_rn(2.0f, a0));
                    float d1 = __fsub_rn(__fadd_rn(znl[s], g_enorm[k1]), __fmul_rn(2.0f, a1));
                    if (d0 < mv[ss] || (d0 == mv[ss] && k0 < mi[ss])) { mv[ss] = d0; mi[ss] = k0; }
                    if (d1 < mv[ss] || (d1 == mv[ss] && k1 < mi[ss])) { mv[ss] = d1; mi[ss] = k1; }
                }
            }
            __syncthreads();
        }
        #pragma unroll
        for (int ss = 0; ss < 2; ++ss) {
            int s = w + ss * 8;
            if (s < 16) { tabv[s * 32 + l] = mv[ss]; tabi[s * 32 + l] = mi[ss]; }
        }
        __syncthreads();
        if (tid < cnt) {
            float bv = tabv[tid * 32];
            int bi = tabi[tid * 32];
            for (int i = 1; i < 32; ++i) {
                float v = tabv[tid * 32 + i];
                int x = tabi[tid * 32 + i];
                if (v < bv || (v == bv && x < bi)) { bv = v; bi = x; }
            }
            fidx[tid] = bi;
        }
        __syncthreads();
        for (int j = tid; j < cnt * 256; j += 256) {
            int s = j >> 8, c = j & 255;
            int px = list[s];
            float zv = Zr[s * 256 + c];
            float e = cb[fidx[s] * CDIM + c];
            out[(size_t)(px >> 12) * (CDIM * HW) + (size_t)c * HW + (px & 4095)] =
                __fadd_rn(zv, __fsub_rn(e, zv));
        }
        __syncthreads();
    }
}

// ---------------- launch ----------------
extern "C" void kernel_launch(void* const* d_in, const int* in_sizes, int n_in,
                              void* d_out, int out_size) {
    const float* z  = (const float*)d_in[0];
    const float* cb = (const float*)d_in[1];
    float* out = (float*)d_out;

    cudaFuncSetAttribute(vq_mma_kernel, cudaFuncAttributeMaxDynamicSharedMemorySize, SMEM_VQ);
    cudaFuncSetAttribute(fallback_kernel, cudaFuncAttributeMaxDynamicSharedMemorySize, SMEM_FB);

    prep_kernel<<<NCODES * CDIM / 256, 256>>>(cb);
    vq_mma_kernel<<<NPIX / PIX_TILE, 512, SMEM_VQ>>>(z, cb, out);
    pair_kernel<<<64, 256>>>(z, cb, out);
    fallback_kernel<<<128, 256, SMEM_FB>>>(z, cb, out);
}

// round 8
// speedup vs baseline: 2.1576x; 1.4772x over previous
#include <cuda_runtime.h>
#include <cuda_fp16.h>
#include <math_constants.h>
#include <cstdint>

#define BATCH 32
#define CDIM 256
#define HW 4096
#define NCODES 1024
#define NPIX (BATCH * HW)
#define PIX_TILE 128
#define THRESH 4.0e-4f

// ---------------- PTX helpers (baseline PTX only) ----------------
__device__ __forceinline__ uint32_t smem_u32(const void* p) {
    uint32_t a;
    asm("{ .reg .u64 t; cvta.to.shared.u64 t, %1; cvt.u32.u64 %0, t; }" : "=r"(a) : "l"(p));
    return a;
}
#define LDSM_X4(r, addr) \
    asm volatile("ldmatrix.sync.aligned.m8n8.x4.shared.b16 {%0,%1,%2,%3}, [%4];" \
        : "=r"((r)[0]), "=r"((r)[1]), "=r"((r)[2]), "=r"((r)[3]) : "r"(addr))
#define MMA16816(d, a, b0, b1) \
    asm volatile("mma.sync.aligned.m16n8k16.row.col.f32.f16.f16.f32 " \
        "{%0,%1,%2,%3}, {%4,%5,%6,%7}, {%8,%9}, {%0,%1,%2,%3};" \
        : "+f"((d)[0]), "+f"((d)[1]), "+f"((d)[2]), "+f"((d)[3]) \
        : "r"((a)[0]), "r"((a)[1]), "r"((a)[2]), "r"((a)[3]), "r"(b0), "r"(b1))
#define CP_ASYNC16(dst, src) \
    asm volatile("cp.async.cg.shared.global [%0], [%1], 16;" :: "r"(dst), "l"(src))
#define CP_COMMIT() asm volatile("cp.async.commit_group;" ::: "memory")
#define CP_WAIT_1() asm volatile("cp.async.wait_group 1;" ::: "memory")
#define CP_WAIT_0() asm volatile("cp.async.wait_group 0;" ::: "memory")

// ---------------- device scratch ----------------
__device__ float  g_enorm[NCODES];
__device__ __half g_cbhi[NCODES * CDIM];
__device__ float  g_zn[NPIX];
__device__ unsigned long long g_best[NPIX];
__device__ int    g_flag[NPIX];
__device__ int    g_nflag;
__device__ int    g_pairA[NPIX];
__device__ int    g_pairB[NPIX];
__device__ int    g_npair;

extern __shared__ float smem[];

// ---------------- prep: fp16 codebook + exact enorm chain + init ----------------
__global__ void prep_kernel(const float* __restrict__ cb) {
    int gid = blockIdx.x * 256 + threadIdx.x;            // 262144 threads
    float v = cb[gid];
    g_cbhi[gid] = __float2half_rn(v);
    if (gid < NPIX) g_best[gid] = ~0ull;
    if (gid < NCODES) {
        const float4* r4 = (const float4*)(cb + gid * CDIM);
        float acc = 0.f;
        #pragma unroll 8
        for (int c4 = 0; c4 < 64; ++c4) {
            float4 w = r4[c4];
            acc = __fadd_rn(acc, __fmul_rn(w.x, w.x));
            acc = __fadd_rn(acc, __fmul_rn(w.y, w.y));
            acc = __fadd_rn(acc, __fmul_rn(w.z, w.z));
            acc = __fadd_rn(acc, __fmul_rn(w.w, w.w));
        }
        g_enorm[gid] = acc;
    }
    if (gid == 0) { g_nflag = 0; g_npair = 0; }
}

// ---------------- main MMA kernel (512 threads, single fp16 product) ----------
// smem bytes:
//   A:    [0, 67584)        128 rows x 528B (256 fp16 z_hi, 16B pad)
//         reused post-mainloop: T1 @0 (16KB), T2 @16384, T3 @32768 (8KB)
//   B:    [67584, 104448)   2 stages x 18432 (128 rows x 144B)
//         reused during A-build as f32 staging (32KB)
//   gbuf: [0, 135168)       output gather, pitch-132 floats (overlaps all above)
//   EN:   [135168, 139264)  1024 f32
//   ZNS:  [139264, 139776)  128 f32
//   IDXF: [139776, 140288)  128 int
#define SB_A    0
#define SB_B    67584
#define SB_T1   0
#define SB_T2   16384
#define SB_T3   32768
#define SB_EN   135168
#define SB_ZNS  139264
#define SB_IDXF 139776
#define SMEM_VQ 140288
#define A_PITCH 528
#define B_PITCH 144
#define B_STAGE 18432

__device__ __forceinline__ void issue_chunk(uint32_t Bs, int it, int tid) {
    int nt = it >> 2, kc = it & 3;
    int r = tid >> 2, q = tid & 3;                       // row 0..127, 128B quarter
    size_t goff = (size_t)(nt * 128 + r) * 512 + kc * 128 + q * 32;
    uint32_t dst = Bs + r * B_PITCH + q * 32;
    const char* ghi = (const char*)g_cbhi + goff;
    CP_ASYNC16(dst,      ghi);
    CP_ASYNC16(dst + 16, ghi + 16);
    CP_COMMIT();
}

__device__ __forceinline__ float keyval(unsigned long long k) {
    return __uint_as_float((uint32_t)(k >> 32));
}
__device__ __forceinline__ unsigned long long mkkey(float d, int code) {
    return ((unsigned long long)__float_as_uint(d) << 32) | (unsigned)code;
}
__device__ __forceinline__ void upd3(unsigned long long key,
                                     unsigned long long& k1, unsigned long long& k2,
                                     float& m3) {
    if (key < k1)      { m3 = keyval(k2); k2 = k1; k1 = key; }
    else if (key < k2) { m3 = keyval(k2); k2 = key; }
    else { float v = keyval(key); if (v < m3) m3 = v; }
}

__global__ __launch_bounds__(512, 1)
void vq_mma_kernel(const float* __restrict__ z, const float* __restrict__ cb,
                   float* __restrict__ out) {
    char* sc = (char*)smem;
    float* Astage = (float*)(sc + SB_B);       // f32 staging during A build
    float* en_s   = (float*)(sc + SB_EN);
    float* zns    = (float*)(sc + SB_ZNS);
    const uint32_t Au = smem_u32(sc + SB_A);
    const uint32_t Bu = smem_u32(sc + SB_B);

    const int tid  = threadIdx.x;
    const int wid  = tid >> 5;
    const int lane = tid & 31;
    const int g = lane >> 2, t = lane & 3;
    const int wm = wid & 3, wn = wid >> 2;     // 4 x 4 warp grid, 32x32 tiles

    const int pb = blockIdx.x;
    const int pix0 = pb * PIX_TILE;
    const int b = pb >> 5;
    const int o4 = ((pb & 31) * PIX_TILE) >> 2;
    const float4* zg4  = (const float4*)z   + (size_t)b * (CDIM * HW / 4);
    float4*       out4 = (float4*)out       + (size_t)b * (CDIM * HW / 4);
    const float4* cb4  = (const float4*)cb;

    for (int j = tid; j < NCODES; j += 512) en_s[j] = g_enorm[j];

    // ---- build A = z_hi fp16 rows + exact zn chains ----
    float znacc = 0.f;
    for (int q = 0; q < 4; ++q) {
        for (int j = tid; j < 64 * 32; j += 512) {
            int cl = j >> 5, v = j & 31;
            ((float4*)Astage)[cl * 32 + v] = zg4[(q * 64 + cl) * (HW / 4) + o4 + v];
        }
        __syncthreads();
        if (tid < 128) {
            char* arow = sc + SB_A + tid * A_PITCH;
            for (int cc = 0; cc < 64; cc += 2) {
                float v0 = Astage[cc * 128 + tid];
                float v1 = Astage[(cc + 1) * 128 + tid];
                znacc = __fadd_rn(znacc, __fmul_rn(v0, v0));
                znacc = __fadd_rn(znacc, __fmul_rn(v1, v1));
                __half h0 = __float2half_rn(v0), h1 = __float2half_rn(v1);
                uint32_t hp = ((uint32_t)__half_as_ushort(h1) << 16) | __half_as_ushort(h0);
                *(uint32_t*)(arow + (q * 64 + cc) * 2) = hp;
            }
        }
        __syncthreads();
    }
    if (tid < 128) { zns[tid] = znacc; g_zn[pix0 + tid] = znacc; }
    __syncthreads();

    // ---- fragment bases ----
    const uint32_t arow  = Au + (wm * 32 + (lane & 15)) * A_PITCH + (lane >> 4) * 16;
    const uint32_t brow0 = Bu + (wn * 32 + ((lane & 7) | ((lane & 16) >> 1))) * B_PITCH
                              + ((lane >> 3) & 1) * 16;
    float zn0[2], zn1[2];
    #pragma unroll
    for (int mi = 0; mi < 2; ++mi) {
        zn0[mi] = zns[wm * 32 + mi * 16 + g];
        zn1[mi] = zns[wm * 32 + mi * 16 + 8 + g];
    }

    unsigned long long K1[4], K2[4];
    float M3[4];
    #pragma unroll
    for (int s = 0; s < 4; ++s) { K1[s] = ~0ull; K2[s] = ~0ull; M3[s] = CUDART_INF_F; }

    float acc[2][4][4];

    // ---- mainloop: 8 N-tiles x 4 K-chunks ----
    issue_chunk(Bu, 0, tid);
    for (int it = 0; it < 32; ++it) {
        const int nt = it >> 2, kc = it & 3;
        if (it + 1 < 32) { issue_chunk(Bu + ((it + 1) & 1) * B_STAGE, it + 1, tid); CP_WAIT_1(); }
        else             { CP_WAIT_0(); }
        __syncthreads();

        if (kc == 0) {
            #pragma unroll
            for (int mi = 0; mi < 2; ++mi)
                #pragma unroll
                for (int j = 0; j < 4; ++j)
                    #pragma unroll
                    for (int r = 0; r < 4; ++r) acc[mi][j][r] = 0.f;
        }

        const uint32_t brow = brow0 + (it & 1) * B_STAGE;
        #pragma unroll
        for (int s = 0; s < 4; ++s) {
            const int kb = (kc * 64 + s * 16) * 2;
            uint32_t ahi[2][4], bhi[2][4];
            #pragma unroll
            for (int mi = 0; mi < 2; ++mi)
                LDSM_X4(ahi[mi], arow + mi * (16 * A_PITCH) + kb);
            #pragma unroll
            for (int nj = 0; nj < 2; ++nj)
                LDSM_X4(bhi[nj], brow + nj * (16 * B_PITCH) + s * 32);
            #pragma unroll
            for (int mi = 0; mi < 2; ++mi)
                #pragma unroll
                for (int j = 0; j < 4; ++j)
                    MMA16816(acc[mi][j], ahi[mi], bhi[j >> 1][(j & 1) * 2], bhi[j >> 1][(j & 1) * 2 + 1]);
        }

        if (kc == 3) {
            #pragma unroll
            for (int mi = 0; mi < 2; ++mi) {
                #pragma unroll
                for (int j = 0; j < 4; ++j) {
                    int cb0 = nt * 128 + wn * 32 + j * 8 + 2 * t;
                    float2 en2 = *(const float2*)(en_s + cb0);
                    float d0 = __fsub_rn(__fadd_rn(zn0[mi], en2.x), __fmul_rn(2.f, acc[mi][j][0]));
                    float d1 = __fsub_rn(__fadd_rn(zn0[mi], en2.y), __fmul_rn(2.f, acc[mi][j][1]));
                    float d2 = __fsub_rn(__fadd_rn(zn1[mi], en2.x), __fmul_rn(2.f, acc[mi][j][2]));
                    float d3 = __fsub_rn(__fadd_rn(zn1[mi], en2.y), __fmul_rn(2.f, acc[mi][j][3]));
                    upd3(mkkey(d0, cb0),     K1[mi * 2],     K2[mi * 2],     M3[mi * 2]);
                    upd3(mkkey(d1, cb0 + 1), K1[mi * 2],     K2[mi * 2],     M3[mi * 2]);
                    upd3(mkkey(d2, cb0),     K1[mi * 2 + 1], K2[mi * 2 + 1], M3[mi * 2 + 1]);
                    upd3(mkkey(d3, cb0 + 1), K1[mi * 2 + 1], K2[mi * 2 + 1], M3[mi * 2 + 1]);
                }
            }
        }
        __syncthreads();
    }

    // ---- cross-thread reduce (16 partials per pixel), global top-3 ----
    unsigned long long* T1 = (unsigned long long*)(sc + SB_T1);
    unsigned long long* T2 = (unsigned long long*)(sc + SB_T2);
    float* T3 = (float*)(sc + SB_T3);
    int* idxf = (int*)(sc + SB_IDXF);
    #pragma unroll
    for (int mi = 0; mi < 2; ++mi)
        #pragma unroll
        for (int half = 0; half < 2; ++half) {
            int pixel = wm * 32 + mi * 16 + half * 8 + g;
            int e = wn * 4 + t;
            T1[pixel * 16 + e] = K1[mi * 2 + half];
            T2[pixel * 16 + e] = K2[mi * 2 + half];
            T3[pixel * 16 + e] = M3[mi * 2 + half];
        }
    __syncthreads();
    if (tid < 128) {
        unsigned long long g1 = ~0ull, g2 = ~0ull;
        float gm3 = CUDART_INF_F;
        #pragma unroll
        for (int e = 0; e < 16; ++e) {
            unsigned long long a = T1[tid * 16 + e], bb = T2[tid * 16 + e];
            float c3 = T3[tid * 16 + e];
            upd3(a, g1, g2, gm3);
            upd3(bb, g1, g2, gm3);
            gm3 = fminf(gm3, c3);
        }
        int i1 = (int)(g1 & 0xffffffffu);
        idxf[tid] = i1;
        float d1 = keyval(g1), d2 = keyval(g2);
        if (gm3 - d1 <= THRESH) {
            int pos = atomicAdd(&g_nflag, 1);
            g_flag[pos] = pix0 + tid;
        } else if (d2 - d1 <= THRESH) {
            int pos = atomicAdd(&g_npair, 1);
            g_pairA[pos] = pix0 + tid;
            g_pairB[pos] = i1 | ((int)(g2 & 0xffffffffu) << 16);
        }
    }
    __syncthreads();

    // ---- fused output: gather + STE write ----
    float* gbuf = (float*)sc;                   // pitch 132
    for (int j = tid; j < PIX_TILE * (CDIM / 4); j += 512) {
        int p = j >> 6, v = j & 63;
        float4 e = cb4[idxf[p] * (CDIM / 4) + v];
        int c = v * 4;
        gbuf[(c + 0) * 132 + p] = e.x;
        gbuf[(c + 1) * 132 + p] = e.y;
        gbuf[(c + 2) * 132 + p] = e.z;
        gbuf[(c + 3) * 132 + p] = e.w;
    }
    __syncthreads();
    for (int i = tid; i < CDIM * (PIX_TILE / 4); i += 512) {
        int c = i >> 5, v = i & 31;
        float4 q = *(const float4*)&gbuf[c * 132 + v * 4];
        float4 zv = zg4[c * (HW / 4) + o4 + v];
        float4 o;
        o.x = __fadd_rn(zv.x, __fsub_rn(q.x, zv.x));
        o.y = __fadd_rn(zv.y, __fsub_rn(q.y, zv.y));
        o.z = __fadd_rn(zv.z, __fsub_rn(q.z, zv.z));
        o.w = __fadd_rn(zv.w, __fsub_rn(q.w, zv.w));
        out4[c * (HW / 4) + o4 + v] = o;
    }
}

// ---------------- pairwise exact resolve (Eigen-chain numerics) ----------------
__global__ __launch_bounds__(256, 4)
void pair_kernel(const float* __restrict__ z, const float* __restrict__ cb,
                 float* __restrict__ out) {
    const int n = g_npair;
    for (int i = blockIdx.x * blockDim.x + threadIdx.x; i < n;
         i += gridDim.x * blockDim.x) {
        int px = g_pairA[i], pk = g_pairB[i];
        int i1 = pk & 0xffff, i2 = (pk >> 16) & 0xffff;
        const float* zp = z + (size_t)(px >> 12) * (CDIM * HW) + (px & 4095);
        const float* c1 = cb + i1 * CDIM;
        const float* c2 = cb + i2 * CDIM;
        float a1 = 0.f, a2 = 0.f;
        #pragma unroll 8
        for (int c = 0; c < CDIM; ++c) {
            float zv = zp[(size_t)c * HW];
            a1 = __fmaf_rn(zv, c1[c], a1);
            a2 = __fmaf_rn(zv, c2[c], a2);
        }
        float zn = g_zn[px];
        float d1 = __fsub_rn(__fadd_rn(zn, g_enorm[i1]), __fmul_rn(2.f, a1));
        float d2 = __fsub_rn(__fadd_rn(zn, g_enorm[i2]), __fmul_rn(2.f, a2));
        int win = (d2 < d1 || (d2 == d1 && i2 < i1)) ? i2 : i1;
        if (win != i1) {
            const float* cw = cb + win * CDIM;
            float* op = out + (size_t)(px >> 12) * (CDIM * HW) + (px & 4095);
            #pragma unroll 8
            for (int c = 0; c < CDIM; ++c) {
                float zv = zp[(size_t)c * HW];
                op[(size_t)c * HW] = __fadd_rn(zv, __fsub_rn(cw[c], zv));
            }
        }
    }
}

// ---------------- full exact fallback: (pixel-group x code-tile) partials ------
// smem: Zr 16x260 f32 (16640B), cbT 64x260 f32 (66560B), list 16 int, znl 16 f32
#define FB_ZR    0
#define FB_CBT   16640
#define FB_LIST  (16640 + 66560)
#define FB_ZN    (FB_LIST + 64)
#define SMEM_FB  (FB_ZN + 64)

__global__ __launch_bounds__(256, 2)
void fb_partial_kernel(const float* __restrict__ z, const float* __restrict__ cb) {
    char* sc = (char*)smem;
    float* Zr   = (float*)(sc + FB_ZR);     // [16][260]
    float* cbT  = (float*)(sc + FB_CBT);    // [64][260]
    int*   list = (int*)(sc + FB_LIST);
    float* znl  = (float*)(sc + FB_ZN);

    const int tid = threadIdx.x;
    const int nf = g_nflag;
    if (nf == 0) return;
    const int nwork = ((nf + 15) >> 4) << 4;          // groups * 16 tiles
    const float4* cb4 = (const float4*)cb;

    for (int w = blockIdx.x; w < nwork; w += gridDim.x) {
        const int pg = w >> 4, kt = w & 15;
        const int cnt = min(16, nf - pg * 16);
        if (tid < cnt) {
            int px = g_flag[pg * 16 + tid];
            list[tid] = px;
            znl[tid] = g_zn[px];
        }
        __syncthreads();
        for (int j = tid; j < cnt * 256; j += 256) {
            int s = j >> 8, c = j & 255;
            int px = list[s];
            Zr[s * 260 + c] = z[(size_t)(px >> 12) * (CDIM * HW) + (size_t)c * HW + (px & 4095)];
        }
        for (int j = tid; j < 64 * 64; j += 256) {
            int r = j >> 6, v4 = j & 63;
            float4 e = cb4[(kt * 64 + r) * 64 + v4];
            *(float4*)&cbT[r * 260 + v4 * 4] = e;
        }
        __syncthreads();

        const int s = tid & 15, kq = tid >> 4;        // pixel slot, code quad
        if (s < cnt) {
            float a0 = 0.f, a1 = 0.f, a2 = 0.f, a3 = 0.f;
            const float4* zr4 = (const float4*)&Zr[s * 260];
            const float4* r0 = (const float4*)&cbT[(kq * 4 + 0) * 260];
            const float4* r1 = (const float4*)&cbT[(kq * 4 + 1) * 260];
            const float4* r2 = (const float4*)&cbT[(kq * 4 + 2) * 260];
            const float4* r3 = (const float4*)&cbT[(kq * 4 + 3) * 260];
            for (int c4 = 0; c4 < 64; ++c4) {         // ascending c, per-code chains
                float4 zq = zr4[c4];
                float4 e0 = r0[c4], e1 = r1[c4], e2 = r2[c4], e3 = r3[c4];
                a0 = __fmaf_rn(zq.x, e0.x, a0); a0 = __fmaf_rn(zq.y, e0.y, a0);
                a0 = __fmaf_rn(zq.z, e0.z, a0); a0 = __fmaf_rn(zq.w, e0.w, a0);
                a1 = __fmaf_rn(zq.x, e1.x, a1); a1 = __fmaf_rn(zq.y, e1.y, a1);
                a1 = __fmaf_rn(zq.z, e1.z, a1); a1 = __fmaf_rn(zq.w, e1.w, a1);
                a2 = __fmaf_rn(zq.x, e2.x, a2); a2 = __fmaf_rn(zq.y, e2.y, a2);
                a2 = __fmaf_rn(zq.z, e2.z, a2); a2 = __fmaf_rn(zq.w, e2.w, a2);
                a3 = __fmaf_rn(zq.x, e3.x, a3); a3 = __fmaf_rn(zq.y, e3.y, a3);
                a3 = __fmaf_rn(zq.z, e3.z, a3); a3 = __fmaf_rn(zq.w, e3.w, a3);
            }
            int k0 = kt * 64 + kq * 4;
            float zn = znl[s];
            float d0 = __fsub_rn(__fadd_rn(zn, g_enorm[k0 + 0]), __fmul_rn(2.f, a0));
            float d1 = __fsub_rn(__fadd_rn(zn, g_enorm[k0 + 1]), __fmul_rn(2.f, a1));
            float d2 = __fsub_rn(__fadd_rn(zn, g_enorm[k0 + 2]), __fmul_rn(2.f, a2));
            float d3 = __fsub_rn(__fadd_rn(zn, g_enorm[k0 + 3]), __fmul_rn(2.f, a3));
            unsigned long long best = mkkey(d0, k0);
            unsigned long long k;
            k = mkkey(d1, k0 + 1); if (k < best) best = k;
            k = mkkey(d2, k0 + 2); if (k < best) best = k;
            k = mkkey(d3, k0 + 3); if (k < best) best = k;
            atomicMin(&g_best[list[s]], best);
        }
        __syncthreads();
    }
}

// ---------------- cleanup: rewrite output rows for flagged pixels --------------
__global__ __launch_bounds__(256, 4)
void cleanup_kernel(const float* __restrict__ z, const float* __restrict__ cb,
                    float* __restrict__ out) {
    const int nf = g_nflag;
    const int c = threadIdx.x;
    for (int i = blockIdx.x; i < nf; i += gridDim.x) {
        int px = g_flag[i];
        int widx = (int)(g_best[px] & 0xffffffffu);
        const float* zp = z + (size_t)(px >> 12) * (CDIM * HW) + (px & 4095);
        float* op = out + (size_t)(px >> 12) * (CDIM * HW) + (px & 4095);
        float zv = zp[(size_t)c * HW];
        float e = cb[widx * CDIM + c];
        op[(size_t)c * HW] = __fadd_rn(zv, __fsub_rn(e, zv));
    }
}

// ---------------- launch ----------------
extern "C" void kernel_launch(void* const* d_in, const int* in_sizes, int n_in,
                              void* d_out, int out_size) {
    const float* z  = (const float*)d_in[0];
    const float* cb = (const float*)d_in[1];
    float* out = (float*)d_out;

    cudaFuncSetAttribute(vq_mma_kernel, cudaFuncAttributeMaxDynamicSharedMemorySize, SMEM_VQ);
    cudaFuncSetAttribute(fb_partial_kernel, cudaFuncAttributeMaxDynamicSharedMemorySize, SMEM_FB);

    prep_kernel<<<NCODES * CDIM / 256, 256>>>(cb);
    vq_mma_kernel<<<NPIX / PIX_TILE, 512, SMEM_VQ>>>(z, cb, out);
    pair_kernel<<<128, 256>>>(z, cb, out);
    fb_partial_kernel<<<2048, 256, SMEM_FB>>>(z, cb);
    cleanup_kernel<<<1024, 256>>>(z, cb, out);
}